// round 2
// baseline (speedup 1.0000x reference)
#include <cuda_runtime.h>
#include <math.h>

// Problem constants (fixed shapes)
#define BB 64      // batch
#define TT 512     // time / bucket_size
#define NU 256     // units
#define N2 512     // 2*units
#define N3 768     // 3*units
#define LN_EPS 1e-5f

// ---------------- scratch (static device arrays; no runtime allocation) ----
__device__ float g_xemb[TT * BB * NU];   // [t][b][c]   33.5 MB
__device__ float g_s1[TT * BB * N3];     // [t][b][768] 100 MB (LN'd in place)
__device__ float g_G[3 * TT * BB * NU];  // conv partial GEMMs, 100 MB

// ---------------- embedding gather ----------------------------------------
// NOTE: token ids are int32 (JAX without x64 downgrades the requested int64).
__global__ void embed_kernel(const int* __restrict__ x,
                             const float* __restrict__ emb) {
    int idx = blockIdx.x * 256 + threadIdx.x;   // grid sized exactly
    int c = idx & 255;
    int b = (idx >> 8) & 63;
    int t = idx >> 14;
    int row = x[(size_t)b * TT + t];
    g_xemb[idx] = emb[(size_t)row * NU + c];
}

// ---------------- generic fp32 tiled GEMM: C = A(MxK) * B(KxN) (+bias) -----
// block tile 64x64, BK=16, 256 threads, 4x4 microtile. M,N,K multiples of tile.
__global__ void __launch_bounds__(256) gemm64(const float* __restrict__ A,
                                              const float* __restrict__ B,
                                              const float* __restrict__ bias,
                                              float* __restrict__ C,
                                              int N, int K) {
    __shared__ float As[64][17];   // [m][k], padded: conflict-free
    __shared__ float Bs[16][64];   // [k][n]

    int tid = threadIdx.x;
    int tx = tid & 15, ty = tid >> 4;
    int row0 = blockIdx.y * 64 + ty * 4;
    int col0 = blockIdx.x * 64 + tx * 4;

    float acc[4][4] = {};
    const float* Ab = A + (size_t)(blockIdx.y * 64) * K;

    for (int k0 = 0; k0 < K; k0 += 16) {
        {   // load A tile: each thread one float4
            int m = tid >> 2, kq = (tid & 3) * 4;
            float4 v = *(const float4*)&Ab[(size_t)m * K + k0 + kq];
            As[m][kq + 0] = v.x; As[m][kq + 1] = v.y;
            As[m][kq + 2] = v.z; As[m][kq + 3] = v.w;
            // load B tile: each thread one float4
            int kb = tid >> 4, nq = (tid & 15) * 4;
            *(float4*)&Bs[kb][nq] =
                *(const float4*)&B[(size_t)(k0 + kb) * N + blockIdx.x * 64 + nq];
        }
        __syncthreads();
        #pragma unroll
        for (int k = 0; k < 16; k++) {
            float4 bv = *(const float4*)&Bs[k][tx * 4];
            float a0 = As[ty * 4 + 0][k], a1 = As[ty * 4 + 1][k];
            float a2 = As[ty * 4 + 2][k], a3 = As[ty * 4 + 3][k];
            acc[0][0] = fmaf(a0, bv.x, acc[0][0]); acc[0][1] = fmaf(a0, bv.y, acc[0][1]);
            acc[0][2] = fmaf(a0, bv.z, acc[0][2]); acc[0][3] = fmaf(a0, bv.w, acc[0][3]);
            acc[1][0] = fmaf(a1, bv.x, acc[1][0]); acc[1][1] = fmaf(a1, bv.y, acc[1][1]);
            acc[1][2] = fmaf(a1, bv.z, acc[1][2]); acc[1][3] = fmaf(a1, bv.w, acc[1][3]);
            acc[2][0] = fmaf(a2, bv.x, acc[2][0]); acc[2][1] = fmaf(a2, bv.y, acc[2][1]);
            acc[2][2] = fmaf(a2, bv.z, acc[2][2]); acc[2][3] = fmaf(a2, bv.w, acc[2][3]);
            acc[3][0] = fmaf(a3, bv.x, acc[3][0]); acc[3][1] = fmaf(a3, bv.y, acc[3][1]);
            acc[3][2] = fmaf(a3, bv.z, acc[3][2]); acc[3][3] = fmaf(a3, bv.w, acc[3][3]);
        }
        __syncthreads();
    }
    #pragma unroll
    for (int i = 0; i < 4; i++) {
        #pragma unroll
        for (int j = 0; j < 4; j++) {
            float v = acc[i][j];
            if (bias) v += bias[col0 + j];
            C[(size_t)(row0 + i) * N + col0 + j] = v;
        }
    }
}

// ---------------- row LayerNorm over 768 cols, in place on g_s1 ------------
__global__ void ln_kernel(const float* __restrict__ gam,
                          const float* __restrict__ bet) {
    int row = blockIdx.x;                    // 32768 rows
    float* p = g_s1 + (size_t)row * N3;
    int tid = threadIdx.x;                   // 256
    float v0 = p[tid], v1 = p[tid + 256], v2 = p[tid + 512];
    float s = v0 + v1 + v2;
    float q = v0 * v0 + v1 * v1 + v2 * v2;
    __shared__ float rs[8], rq[8];
    __shared__ float tot[2];
    int lane = tid & 31, w = tid >> 5;
    #pragma unroll
    for (int o = 16; o; o >>= 1) {
        s += __shfl_down_sync(0xffffffffu, s, o);
        q += __shfl_down_sync(0xffffffffu, q, o);
    }
    if (!lane) { rs[w] = s; rq[w] = q; }
    __syncthreads();
    if (tid == 0) {
        float S = 0, Q = 0;
        for (int i = 0; i < 8; i++) { S += rs[i]; Q += rq[i]; }
        tot[0] = S; tot[1] = Q;
    }
    __syncthreads();
    float mean = tot[0] * (1.0f / 768.0f);
    float var = fmaxf(tot[1] * (1.0f / 768.0f) - mean * mean, 0.0f);
    float inv = 1.0f / (sqrtf(var + LN_EPS) + LN_EPS);
    p[tid]       = gam[tid]       * ((v0 - mean) * inv) + bet[tid];
    p[tid + 256] = gam[tid + 256] * ((v1 - mean) * inv) + bet[tid + 256];
    p[tid + 512] = gam[tid + 512] * ((v2 - mean) * inv) + bet[tid + 512];
}

// ---------------- conv shift-add + max over time ---------------------------
__global__ void maxcomb_kernel(float* __restrict__ out) {
    int b = blockIdx.x;        // 64
    int f = threadIdx.x;       // 256
    const float* G0 = g_G;
    const float* G1 = g_G + (size_t)TT * BB * NU;
    const float* G2 = g_G + (size_t)2 * TT * BB * NU;
    float m = -INFINITY;
    #pragma unroll 4
    for (int tp = 0; tp < 510; tp++) {
        size_t i0 = ((size_t)tp * 64 + b) * 256 + f;
        float v = G0[i0] + G1[i0 + 64 * 256] + G2[i0 + 2 * 64 * 256];
        m = fmaxf(m, v);
    }
    out[(size_t)b * 512 + 256 + f] = m;
}

// ---------------- recurrence: 32 CTAs x 2 batch rows, 512 threads ----------
// smem: U rows 0..63 cached (192KB) + h/rh/z/partials/reduction scratch
#define REC_SMEM_FLOATS (64 * 768 + 4 * 512 + 64 + 4)
__device__ __forceinline__ float hsig(float v) {
    return fminf(fmaxf(0.2f * v + 0.5f, 0.0f), 1.0f);
}

__global__ void __launch_bounds__(512, 1) rec_kernel(
    const int* __restrict__ x, const float* __restrict__ Umat,
    const float* __restrict__ s1, const float* __restrict__ gammas,
    const float* __restrict__ betas, float* __restrict__ out) {
    extern __shared__ float sm[];
    float* sU   = sm;                    // 64*768
    float* sh   = sU + 64 * 768;         // h: [2][256]
    float* srh  = sh + 512;              // r*h: [2][256]
    float* sz   = srh + 512;             // z:  [2][256]
    float* sprt = sz + 512;              // phase-B partials [2][256]
    float* sred = sprt + 512;            // 64
    float* sstat = sred + 64;            // 4

    int tid = threadIdx.x;
    int b0 = blockIdx.x * 2, b1 = b0 + 1;
    int lane = tid & 31, wid = tid >> 5;
    int c = tid;                 // 0..511
    int c2 = tid & 255;
    int half = tid >> 8;

    const float* g1 = gammas + 768;
    const float* be1 = betas + 768;
    float g1c = g1[c], be1c = be1[c];
    float g1c3 = g1[512 + c2], be1c3 = be1[512 + c2];

    // preload U rows 0..63 (full 768 cols), init h = 0
    for (int i = tid; i < 64 * 768 / 4; i += 512)
        ((float4*)sU)[i] = ((const float4*)Umat)[i];
    if (tid < 256) { sh[tid] = 0.0f; sh[256 + tid] = 0.0f; }
    __syncthreads();

    for (int t = 0; t < TT; t++) {
        bool m0 = x[(size_t)b0 * TT + t] != 0;
        bool m1 = x[(size_t)b1 * TT + t] != 0;
        const float* s1r0 = s1 + ((size_t)t * 64 + b0) * N3;
        const float* s1r1 = s1 + ((size_t)t * 64 + b1) * N3;
        float s1a0 = s1r0[c], s1a1 = s1r1[c];
        float s1c0 = 0.0f, s1c1 = 0.0f;
        if (half == 0) { s1c0 = s1r0[512 + c2]; s1c1 = s1r1[512 + c2]; }

        // -------- phase A: s2pre = h @ U[:, :512], thread owns col c ------
        float a0 = 0.0f, a1 = 0.0f;
        #pragma unroll
        for (int k = 0; k < 64; k += 4) {
            float4 h0v = *(const float4*)&sh[k];
            float4 h1v = *(const float4*)&sh[256 + k];
            float u0 = sU[(k + 0) * 768 + c], u1 = sU[(k + 1) * 768 + c];
            float u2 = sU[(k + 2) * 768 + c], u3 = sU[(k + 3) * 768 + c];
            a0 = fmaf(h0v.x, u0, fmaf(h0v.y, u1, fmaf(h0v.z, u2, fmaf(h0v.w, u3, a0))));
            a1 = fmaf(h1v.x, u0, fmaf(h1v.y, u1, fmaf(h1v.z, u2, fmaf(h1v.w, u3, a1))));
        }
        #pragma unroll 8
        for (int k = 64; k < 256; k += 4) {
            float4 h0v = *(const float4*)&sh[k];
            float4 h1v = *(const float4*)&sh[256 + k];
            const float* up = &Umat[(size_t)k * 768 + c];
            float u0 = __ldg(up), u1 = __ldg(up + 768);
            float u2 = __ldg(up + 1536), u3 = __ldg(up + 2304);
            a0 = fmaf(h0v.x, u0, fmaf(h0v.y, u1, fmaf(h0v.z, u2, fmaf(h0v.w, u3, a0))));
            a1 = fmaf(h1v.x, u0, fmaf(h1v.y, u1, fmaf(h1v.z, u2, fmaf(h1v.w, u3, a1))));
        }
        // LN stats over 512 cols for both rows
        {
            float p0 = a0, q0 = a0 * a0, p1 = a1, q1 = a1 * a1;
            #pragma unroll
            for (int o = 16; o; o >>= 1) {
                p0 += __shfl_down_sync(0xffffffffu, p0, o);
                q0 += __shfl_down_sync(0xffffffffu, q0, o);
                p1 += __shfl_down_sync(0xffffffffu, p1, o);
                q1 += __shfl_down_sync(0xffffffffu, q1, o);
            }
            if (!lane) {
                sred[wid] = p0; sred[16 + wid] = q0;
                sred[32 + wid] = p1; sred[48 + wid] = q1;
            }
        }
        __syncthreads();
        if (tid < 4) {
            float s = 0;
            for (int i = 0; i < 16; i++) s += sred[tid * 16 + i];
            sstat[tid] = s;
        }
        __syncthreads();
        {
            float mean0 = sstat[0] * (1.0f / 512.0f);
            float var0 = fmaxf(sstat[1] * (1.0f / 512.0f) - mean0 * mean0, 0.0f);
            float inv0 = 1.0f / (sqrtf(var0 + LN_EPS) + LN_EPS);
            float mean1 = sstat[2] * (1.0f / 512.0f);
            float var1 = fmaxf(sstat[3] * (1.0f / 512.0f) - mean1 * mean1, 0.0f);
            float inv1 = 1.0f / (sqrtf(var1 + LN_EPS) + LN_EPS);
            float sv0 = hsig(s1a0 + g1c * ((a0 - mean0) * inv0) + be1c);
            float sv1 = hsig(s1a1 + g1c * ((a1 - mean1) * inv1) + be1c);
            if (c < 256) { sz[c] = sv0; sz[256 + c] = sv1; }
            else {
                srh[c - 256]       = sv0 * sh[c - 256];
                srh[256 + (c - 256)] = sv1 * sh[256 + (c - 256)];
            }
        }
        __syncthreads();

        // -------- phase B: (r*h) @ U[:, 512:], split k across halves ------
        float t0 = 0.0f, t1 = 0.0f;
        if (half == 0) {
            #pragma unroll
            for (int k = 0; k < 64; k += 4) {
                float4 r0v = *(const float4*)&srh[k];
                float4 r1v = *(const float4*)&srh[256 + k];
                float u0 = sU[(k + 0) * 768 + 512 + c2], u1 = sU[(k + 1) * 768 + 512 + c2];
                float u2 = sU[(k + 2) * 768 + 512 + c2], u3 = sU[(k + 3) * 768 + 512 + c2];
                t0 = fmaf(r0v.x, u0, fmaf(r0v.y, u1, fmaf(r0v.z, u2, fmaf(r0v.w, u3, t0))));
                t1 = fmaf(r1v.x, u0, fmaf(r1v.y, u1, fmaf(r1v.z, u2, fmaf(r1v.w, u3, t1))));
            }
            #pragma unroll 8
            for (int k = 64; k < 128; k += 4) {
                float4 r0v = *(const float4*)&srh[k];
                float4 r1v = *(const float4*)&srh[256 + k];
                const float* up = &Umat[(size_t)k * 768 + 512 + c2];
                float u0 = __ldg(up), u1 = __ldg(up + 768);
                float u2 = __ldg(up + 1536), u3 = __ldg(up + 2304);
                t0 = fmaf(r0v.x, u0, fmaf(r0v.y, u1, fmaf(r0v.z, u2, fmaf(r0v.w, u3, t0))));
                t1 = fmaf(r1v.x, u0, fmaf(r1v.y, u1, fmaf(r1v.z, u2, fmaf(r1v.w, u3, t1))));
            }
        } else {
            #pragma unroll 8
            for (int k = 128; k < 256; k += 4) {
                float4 r0v = *(const float4*)&srh[k];
                float4 r1v = *(const float4*)&srh[256 + k];
                const float* up = &Umat[(size_t)k * 768 + 512 + c2];
                float u0 = __ldg(up), u1 = __ldg(up + 768);
                float u2 = __ldg(up + 1536), u3 = __ldg(up + 2304);
                t0 = fmaf(r0v.x, u0, fmaf(r0v.y, u1, fmaf(r0v.z, u2, fmaf(r0v.w, u3, t0))));
                t1 = fmaf(r1v.x, u0, fmaf(r1v.y, u1, fmaf(r1v.z, u2, fmaf(r1v.w, u3, t1))));
            }
        }
        if (half == 1) { sprt[c2] = t0; sprt[256 + c2] = t1; }
        __syncthreads();
        float tot0 = 0.0f, tot1 = 0.0f;
        if (half == 0) {
            tot0 = t0 + sprt[c2];
            tot1 = t1 + sprt[256 + c2];
            float p0 = tot0, q0 = tot0 * tot0, p1 = tot1, q1 = tot1 * tot1;
            #pragma unroll
            for (int o = 16; o; o >>= 1) {
                p0 += __shfl_down_sync(0xffffffffu, p0, o);
                q0 += __shfl_down_sync(0xffffffffu, q0, o);
                p1 += __shfl_down_sync(0xffffffffu, p1, o);
                q1 += __shfl_down_sync(0xffffffffu, q1, o);
            }
            if (!lane) {
                sred[wid] = p0; sred[8 + wid] = q0;
                sred[16 + wid] = p1; sred[24 + wid] = q1;
            }
        }
        __syncthreads();
        if (tid < 4) {
            float s = 0;
            for (int i = 0; i < 8; i++) s += sred[tid * 8 + i];
            sstat[tid] = s;
        }
        __syncthreads();

        // -------- phase C: hc = tanh(s1c + LN3), gate, masked update ------
        if (half == 0) {
            float mean0 = sstat[0] * (1.0f / 256.0f);
            float var0 = fmaxf(sstat[1] * (1.0f / 256.0f) - mean0 * mean0, 0.0f);
            float inv0 = 1.0f / (sqrtf(var0 + LN_EPS) + LN_EPS);
            float mean1 = sstat[2] * (1.0f / 256.0f);
            float var1 = fmaxf(sstat[3] * (1.0f / 256.0f) - mean1 * mean1, 0.0f);
            float inv1 = 1.0f / (sqrtf(var1 + LN_EPS) + LN_EPS);
            float hc0 = tanhf(s1c0 + g1c3 * ((tot0 - mean0) * inv0) + be1c3);
            float hc1 = tanhf(s1c1 + g1c3 * ((tot1 - mean1) * inv1) + be1c3);
            float z0 = sz[c2], z1 = sz[256 + c2];
            float h0 = sh[c2], h1 = sh[256 + c2];
            float hn0 = z0 * h0 + (1.0f - z0) * hc0;
            float hn1 = z1 * h1 + (1.0f - z1) * hc1;
            sh[c2]       = m0 ? hn0 : h0;
            sh[256 + c2] = m1 ? hn1 : h1;
        }
        __syncthreads();
    }

    if (half == 0) {
        out[(size_t)b0 * 512 + c2] = sh[c2];
        out[(size_t)b1 * 512 + c2] = sh[256 + c2];
    }
}

// ---------------- launch ---------------------------------------------------
extern "C" void kernel_launch(void* const* d_in, const int* in_sizes, int n_in,
                              void* d_out, int out_size) {
    const int* x           = (const int*)d_in[0];   // token ids (int32)
    // d_in[1] = bucket_size (constant 512, unused)
    const float* emb       = (const float*)d_in[2];
    const float* W         = (const float*)d_in[3];
    const float* Umat      = (const float*)d_in[4];
    const float* bias      = (const float*)d_in[5];
    const float* gammas    = (const float*)d_in[6];
    const float* betas     = (const float*)d_in[7];
    const float* kern      = (const float*)d_in[8];
    float* out             = (float*)d_out;

    float *xe, *s1p, *gp;
    cudaGetSymbolAddress((void**)&xe, g_xemb);
    cudaGetSymbolAddress((void**)&s1p, g_s1);
    cudaGetSymbolAddress((void**)&gp, g_G);

    // 1) embedding gather
    embed_kernel<<<TT * BB, 256>>>(x, emb);
    // 2) s1 = x_emb @ W + b, then LN in place
    gemm64<<<dim3(N3 / 64, TT * BB / 64), 256>>>(xe, W, bias, s1p, N3, NU);
    ln_kernel<<<TT * BB, 256>>>(gammas, betas);
    // 3) recurrence (dominant, sequential)
    static const size_t rec_smem = REC_SMEM_FLOATS * sizeof(float);
    cudaFuncSetAttribute(rec_kernel, cudaFuncAttributeMaxDynamicSharedMemorySize,
                         (int)rec_smem);
    rec_kernel<<<32, 512, rec_smem>>>(x, Umat, s1p, gammas, betas, out);
    // 4) conv as 3 shifted GEMMs + max combine
    for (int k = 0; k < 3; k++)
        gemm64<<<dim3(NU / 64, TT * BB / 64), 256>>>(
            xe, kern + (size_t)k * NU * NU, nullptr,
            gp + (size_t)k * TT * BB * NU, NU, NU);
    maxcomb_kernel<<<BB, 256>>>(out);
}

// round 3
// speedup vs baseline: 1.0385x; 1.0385x over previous
#include <cuda_runtime.h>
#include <math.h>

// Problem constants (fixed shapes)
#define BB 64      // batch
#define TT 512     // time / bucket_size
#define NU 256     // units
#define N2 512     // 2*units
#define N3 768     // 3*units
#define LN_EPS 1e-5f

typedef unsigned long long ull;
typedef unsigned int uint;

// ---------------- scratch (static device arrays; no runtime allocation) ----
__device__ float g_xemb[TT * BB * NU];   // [t][b][c]   33.5 MB
__device__ float g_s1[TT * BB * N3];     // [t][b][768] 100 MB (LN'd in place)
__device__ uint  g_enc[BB * NU];         // encoded running max for conv

// ---------------- embedding gather ----------------------------------------
// NOTE: token ids are int32 (JAX without x64 downgrades the requested int64).
__global__ void embed_kernel(const int* __restrict__ x,
                             const float* __restrict__ emb) {
    int idx = blockIdx.x * 256 + threadIdx.x;   // grid sized exactly
    int c = idx & 255;
    int b = (idx >> 8) & 63;
    int t = idx >> 14;
    int row = x[(size_t)b * TT + t];
    g_xemb[idx] = emb[(size_t)row * NU + c];
}

// ---------------- monotone float<->uint encoding for atomicMax -------------
__device__ __forceinline__ uint enc_f(float v) {
    uint u = __float_as_uint(v);
    return ((int)u < 0) ? ~u : (u | 0x80000000u);
}
__device__ __forceinline__ float dec_f(uint e) {
    uint u = (e & 0x80000000u) ? (e ^ 0x80000000u) : ~e;
    return __uint_as_float(u);
}

__global__ void encinit_kernel() {
    g_enc[blockIdx.x * 256 + threadIdx.x] = enc_f(-INFINITY);
}
__global__ void decode_kernel(float* __restrict__ out) {
    int f = threadIdx.x;           // 256
    int b = blockIdx.x;            // 64
    out[(size_t)b * 512 + 256 + f] = dec_f(g_enc[b * 256 + f]);
}

// ---------------- 128x128 fp32 GEMM with f32x2 packed FMAs -----------------
// C(MxN) = A(Mx K) * B(KxN)   [A is g_xemb with the 3-tap "segment" address:
//   A[row,k] = g_xemb[row*256 + (k>>8)*16384 + (k&255)]  — for K=256 this is
//   plain row-major; for K=768 it realizes the width-3 conv as one GEMM.]
// If C != null: store (plus bias). If domax: fused atomicMax into g_enc.
#define SP_A 132
__global__ void __launch_bounds__(256, 2)
gemm128(const float* __restrict__ A, const float* __restrict__ B,
        const float* __restrict__ bias, float* __restrict__ C,
        int N, int K, int domax) {
    __shared__ float As[2][8 * SP_A];
    __shared__ float Bs[2][8 * 128];

    int tid = threadIdx.x;
    int tx = tid & 15, ty = tid >> 4;
    int r0 = blockIdx.y * 128, c0 = blockIdx.x * 128;

    // gmem staging roles
    int am = tid >> 1, akq = (tid & 1) * 4;    // A: row am, k sub-offset
    int bk = tid >> 5, bn = (tid & 31) * 4;    // B: k row bk, col bn

    ull acc[8][4];
    #pragma unroll
    for (int i = 0; i < 8; i++)
        #pragma unroll
        for (int j = 0; j < 4; j++) acc[i][j] = 0ull;

    const float* Arow = A + (size_t)(r0 + am) * 256;

    // prefetch tile 0
    int k = akq;
    float4 aR = *(const float4*)&Arow[((k >> 8) << 14) + (k & 255)];
    float4 bR = *(const float4*)&B[(size_t)bk * N + c0 + bn];
    {
        float* as = As[0];
        as[(akq + 0) * SP_A + am] = aR.x;
        as[(akq + 1) * SP_A + am] = aR.y;
        as[(akq + 2) * SP_A + am] = aR.z;
        as[(akq + 3) * SP_A + am] = aR.w;
        *(float4*)&Bs[0][bk * 128 + bn] = bR;
    }
    __syncthreads();

    int buf = 0;
    for (int k0 = 0; k0 < K; k0 += 8) {
        bool more = (k0 + 8) < K;
        if (more) {
            k = k0 + 8 + akq;
            aR = *(const float4*)&Arow[((k >> 8) << 14) + (k & 255)];
            bR = *(const float4*)&B[(size_t)(k0 + 8 + bk) * N + c0 + bn];
        }
        const float* as = As[buf];
        const float* bs = Bs[buf];
        #pragma unroll
        for (int kk = 0; kk < 8; kk++) {
            float4 a0 = *(const float4*)&as[kk * SP_A + ty * 8];
            float4 a1 = *(const float4*)&as[kk * SP_A + ty * 8 + 4];
            float4 b0 = *(const float4*)&bs[kk * 128 + tx * 8];
            float4 b1 = *(const float4*)&bs[kk * 128 + tx * 8 + 4];
            ull pb[4];
            asm("mov.b64 %0, {%1, %2};" : "=l"(pb[0]) : "f"(b0.x), "f"(b0.y));
            asm("mov.b64 %0, {%1, %2};" : "=l"(pb[1]) : "f"(b0.z), "f"(b0.w));
            asm("mov.b64 %0, {%1, %2};" : "=l"(pb[2]) : "f"(b1.x), "f"(b1.y));
            asm("mov.b64 %0, {%1, %2};" : "=l"(pb[3]) : "f"(b1.z), "f"(b1.w));
            float av[8] = {a0.x, a0.y, a0.z, a0.w, a1.x, a1.y, a1.z, a1.w};
            #pragma unroll
            for (int i = 0; i < 8; i++) {
                ull pa;
                asm("mov.b64 %0, {%1, %1};" : "=l"(pa) : "f"(av[i]));
                #pragma unroll
                for (int j = 0; j < 4; j++)
                    asm("fma.rn.f32x2 %0, %1, %2, %0;"
                        : "+l"(acc[i][j]) : "l"(pa), "l"(pb[j]));
            }
        }
        if (more) {
            float* asn = As[buf ^ 1];
            asn[(akq + 0) * SP_A + am] = aR.x;
            asn[(akq + 1) * SP_A + am] = aR.y;
            asn[(akq + 2) * SP_A + am] = aR.z;
            asn[(akq + 3) * SP_A + am] = aR.w;
            *(float4*)&Bs[buf ^ 1][bk * 128 + bn] = bR;
        }
        __syncthreads();
        buf ^= 1;
    }

    // epilogue
    float bv[8];
    if (bias) {
        #pragma unroll
        for (int j = 0; j < 8; j++) bv[j] = bias[c0 + tx * 8 + j];
    }
    #pragma unroll
    for (int i = 0; i < 8; i++) {
        int row = r0 + ty * 8 + i;
        float v[8];
        #pragma unroll
        for (int j = 0; j < 4; j++) {
            v[2 * j]     = __uint_as_float((uint)(acc[i][j] & 0xffffffffull));
            v[2 * j + 1] = __uint_as_float((uint)(acc[i][j] >> 32));
        }
        if (bias) {
            #pragma unroll
            for (int j = 0; j < 8; j++) v[j] += bv[j];
        }
        if (C) {
            float4 s0 = make_float4(v[0], v[1], v[2], v[3]);
            float4 s1 = make_float4(v[4], v[5], v[6], v[7]);
            *(float4*)&C[(size_t)row * N + c0 + tx * 8] = s0;
            *(float4*)&C[(size_t)row * N + c0 + tx * 8 + 4] = s1;
        }
        if (domax) {
            int b = row & 63;
            #pragma unroll
            for (int j = 0; j < 8; j++)
                atomicMax(&g_enc[b * 256 + c0 + tx * 8 + j], enc_f(v[j]));
        }
    }
}

// ---------------- row LayerNorm over 768 cols, in place on g_s1 ------------
__global__ void ln_kernel(const float* __restrict__ gam,
                          const float* __restrict__ bet) {
    int row = blockIdx.x;                    // 32768 rows
    float* p = g_s1 + (size_t)row * N3;
    int tid = threadIdx.x;                   // 256
    float v0 = p[tid], v1 = p[tid + 256], v2 = p[tid + 512];
    float s = v0 + v1 + v2;
    float q = v0 * v0 + v1 * v1 + v2 * v2;
    __shared__ float rs[8], rq[8];
    __shared__ float tot[2];
    int lane = tid & 31, w = tid >> 5;
    #pragma unroll
    for (int o = 16; o; o >>= 1) {
        s += __shfl_down_sync(0xffffffffu, s, o);
        q += __shfl_down_sync(0xffffffffu, q, o);
    }
    if (!lane) { rs[w] = s; rq[w] = q; }
    __syncthreads();
    if (tid == 0) {
        float S = 0, Q = 0;
        for (int i = 0; i < 8; i++) { S += rs[i]; Q += rq[i]; }
        tot[0] = S; tot[1] = Q;
    }
    __syncthreads();
    float mean = tot[0] * (1.0f / 768.0f);
    float var = fmaxf(tot[1] * (1.0f / 768.0f) - mean * mean, 0.0f);
    float inv = 1.0f / (sqrtf(var + LN_EPS) + LN_EPS);
    p[tid]       = gam[tid]       * ((v0 - mean) * inv) + bet[tid];
    p[tid + 256] = gam[tid + 256] * ((v1 - mean) * inv) + bet[tid + 256];
    p[tid + 512] = gam[tid + 512] * ((v2 - mean) * inv) + bet[tid + 512];
}

// ---------------- recurrence: 32 CTAs x 2 batch rows, 512 threads ----------
// smem: U rows 0..63 cached (192KB) + h/rh/z/partials/reduction scratch
#define REC_SMEM_FLOATS (64 * 768 + 4 * 512 + 64 + 4)
__device__ __forceinline__ float hsig(float v) {
    return fminf(fmaxf(0.2f * v + 0.5f, 0.0f), 1.0f);
}

__global__ void __launch_bounds__(512, 1) rec_kernel(
    const int* __restrict__ x, const float* __restrict__ Umat,
    const float* __restrict__ s1, const float* __restrict__ gammas,
    const float* __restrict__ betas, float* __restrict__ out) {
    extern __shared__ float sm[];
    float* sU   = sm;                    // 64*768
    float* sh   = sU + 64 * 768;         // h: [2][256]
    float* srh  = sh + 512;              // r*h: [2][256]
    float* sz   = srh + 512;             // z:  [2][256]
    float* sprt = sz + 512;              // phase-B partials [2][256]
    float* sred = sprt + 512;            // 64
    float* sstat = sred + 64;            // 4

    int tid = threadIdx.x;
    int b0 = blockIdx.x * 2, b1 = b0 + 1;
    int lane = tid & 31, wid = tid >> 5;
    int c = tid;                 // 0..511
    int c2 = tid & 255;
    int half = tid >> 8;

    const float* g1 = gammas + 768;
    const float* be1 = betas + 768;
    float g1c = g1[c], be1c = be1[c];
    float g1c3 = g1[512 + c2], be1c3 = be1[512 + c2];

    // preload U rows 0..63 (full 768 cols), init h = 0
    for (int i = tid; i < 64 * 768 / 4; i += 512)
        ((float4*)sU)[i] = ((const float4*)Umat)[i];
    if (tid < 256) { sh[tid] = 0.0f; sh[256 + tid] = 0.0f; }
    __syncthreads();

    for (int t = 0; t < TT; t++) {
        bool m0 = x[(size_t)b0 * TT + t] != 0;
        bool m1 = x[(size_t)b1 * TT + t] != 0;
        const float* s1r0 = s1 + ((size_t)t * 64 + b0) * N3;
        const float* s1r1 = s1 + ((size_t)t * 64 + b1) * N3;
        float s1a0 = s1r0[c], s1a1 = s1r1[c];
        float s1c0 = 0.0f, s1c1 = 0.0f;
        if (half == 0) { s1c0 = s1r0[512 + c2]; s1c1 = s1r1[512 + c2]; }

        // -------- phase A: s2pre = h @ U[:, :512], thread owns col c ------
        float a0 = 0.0f, a1 = 0.0f;
        #pragma unroll
        for (int k = 0; k < 64; k += 4) {
            float4 h0v = *(const float4*)&sh[k];
            float4 h1v = *(const float4*)&sh[256 + k];
            float u0 = sU[(k + 0) * 768 + c], u1 = sU[(k + 1) * 768 + c];
            float u2 = sU[(k + 2) * 768 + c], u3 = sU[(k + 3) * 768 + c];
            a0 = fmaf(h0v.x, u0, fmaf(h0v.y, u1, fmaf(h0v.z, u2, fmaf(h0v.w, u3, a0))));
            a1 = fmaf(h1v.x, u0, fmaf(h1v.y, u1, fmaf(h1v.z, u2, fmaf(h1v.w, u3, a1))));
        }
        #pragma unroll 8
        for (int k = 64; k < 256; k += 4) {
            float4 h0v = *(const float4*)&sh[k];
            float4 h1v = *(const float4*)&sh[256 + k];
            const float* up = &Umat[(size_t)k * 768 + c];
            float u0 = __ldg(up), u1 = __ldg(up + 768);
            float u2 = __ldg(up + 1536), u3 = __ldg(up + 2304);
            a0 = fmaf(h0v.x, u0, fmaf(h0v.y, u1, fmaf(h0v.z, u2, fmaf(h0v.w, u3, a0))));
            a1 = fmaf(h1v.x, u0, fmaf(h1v.y, u1, fmaf(h1v.z, u2, fmaf(h1v.w, u3, a1))));
        }
        // LN stats over 512 cols for both rows
        {
            float p0 = a0, q0 = a0 * a0, p1 = a1, q1 = a1 * a1;
            #pragma unroll
            for (int o = 16; o; o >>= 1) {
                p0 += __shfl_down_sync(0xffffffffu, p0, o);
                q0 += __shfl_down_sync(0xffffffffu, q0, o);
                p1 += __shfl_down_sync(0xffffffffu, p1, o);
                q1 += __shfl_down_sync(0xffffffffu, q1, o);
            }
            if (!lane) {
                sred[wid] = p0; sred[16 + wid] = q0;
                sred[32 + wid] = p1; sred[48 + wid] = q1;
            }
        }
        __syncthreads();
        if (tid < 4) {
            float s = 0;
            for (int i = 0; i < 16; i++) s += sred[tid * 16 + i];
            sstat[tid] = s;
        }
        __syncthreads();
        {
            float mean0 = sstat[0] * (1.0f / 512.0f);
            float var0 = fmaxf(sstat[1] * (1.0f / 512.0f) - mean0 * mean0, 0.0f);
            float inv0 = 1.0f / (sqrtf(var0 + LN_EPS) + LN_EPS);
            float mean1 = sstat[2] * (1.0f / 512.0f);
            float var1 = fmaxf(sstat[3] * (1.0f / 512.0f) - mean1 * mean1, 0.0f);
            float inv1 = 1.0f / (sqrtf(var1 + LN_EPS) + LN_EPS);
            float sv0 = hsig(s1a0 + g1c * ((a0 - mean0) * inv0) + be1c);
            float sv1 = hsig(s1a1 + g1c * ((a1 - mean1) * inv1) + be1c);
            if (c < 256) { sz[c] = sv0; sz[256 + c] = sv1; }
            else {
                srh[c - 256]       = sv0 * sh[c - 256];
                srh[256 + (c - 256)] = sv1 * sh[256 + (c - 256)];
            }
        }
        __syncthreads();

        // -------- phase B: (r*h) @ U[:, 512:], split k across halves ------
        float t0 = 0.0f, t1 = 0.0f;
        if (half == 0) {
            #pragma unroll
            for (int k = 0; k < 64; k += 4) {
                float4 r0v = *(const float4*)&srh[k];
                float4 r1v = *(const float4*)&srh[256 + k];
                float u0 = sU[(k + 0) * 768 + 512 + c2], u1 = sU[(k + 1) * 768 + 512 + c2];
                float u2 = sU[(k + 2) * 768 + 512 + c2], u3 = sU[(k + 3) * 768 + 512 + c2];
                t0 = fmaf(r0v.x, u0, fmaf(r0v.y, u1, fmaf(r0v.z, u2, fmaf(r0v.w, u3, t0))));
                t1 = fmaf(r1v.x, u0, fmaf(r1v.y, u1, fmaf(r1v.z, u2, fmaf(r1v.w, u3, t1))));
            }
            #pragma unroll 8
            for (int k = 64; k < 128; k += 4) {
                float4 r0v = *(const float4*)&srh[k];
                float4 r1v = *(const float4*)&srh[256 + k];
                const float* up = &Umat[(size_t)k * 768 + 512 + c2];
                float u0 = __ldg(up), u1 = __ldg(up + 768);
                float u2 = __ldg(up + 1536), u3 = __ldg(up + 2304);
                t0 = fmaf(r0v.x, u0, fmaf(r0v.y, u1, fmaf(r0v.z, u2, fmaf(r0v.w, u3, t0))));
                t1 = fmaf(r1v.x, u0, fmaf(r1v.y, u1, fmaf(r1v.z, u2, fmaf(r1v.w, u3, t1))));
            }
        } else {
            #pragma unroll 8
            for (int k = 128; k < 256; k += 4) {
                float4 r0v = *(const float4*)&srh[k];
                float4 r1v = *(const float4*)&srh[256 + k];
                const float* up = &Umat[(size_t)k * 768 + 512 + c2];
                float u0 = __ldg(up), u1 = __ldg(up + 768);
                float u2 = __ldg(up + 1536), u3 = __ldg(up + 2304);
                t0 = fmaf(r0v.x, u0, fmaf(r0v.y, u1, fmaf(r0v.z, u2, fmaf(r0v.w, u3, t0))));
                t1 = fmaf(r1v.x, u0, fmaf(r1v.y, u1, fmaf(r1v.z, u2, fmaf(r1v.w, u3, t1))));
            }
        }
        if (half == 1) { sprt[c2] = t0; sprt[256 + c2] = t1; }
        __syncthreads();
        float tot0 = 0.0f, tot1 = 0.0f;
        if (half == 0) {
            tot0 = t0 + sprt[c2];
            tot1 = t1 + sprt[256 + c2];
            float p0 = tot0, q0 = tot0 * tot0, p1 = tot1, q1 = tot1 * tot1;
            #pragma unroll
            for (int o = 16; o; o >>= 1) {
                p0 += __shfl_down_sync(0xffffffffu, p0, o);
                q0 += __shfl_down_sync(0xffffffffu, q0, o);
                p1 += __shfl_down_sync(0xffffffffu, p1, o);
                q1 += __shfl_down_sync(0xffffffffu, q1, o);
            }
            if (!lane) {
                sred[wid] = p0; sred[8 + wid] = q0;
                sred[16 + wid] = p1; sred[24 + wid] = q1;
            }
        }
        __syncthreads();
        if (tid < 4) {
            float s = 0;
            for (int i = 0; i < 8; i++) s += sred[tid * 8 + i];
            sstat[tid] = s;
        }
        __syncthreads();

        // -------- phase C: hc = tanh(s1c + LN3), gate, masked update ------
        if (half == 0) {
            float mean0 = sstat[0] * (1.0f / 256.0f);
            float var0 = fmaxf(sstat[1] * (1.0f / 256.0f) - mean0 * mean0, 0.0f);
            float inv0 = 1.0f / (sqrtf(var0 + LN_EPS) + LN_EPS);
            float mean1 = sstat[2] * (1.0f / 256.0f);
            float var1 = fmaxf(sstat[3] * (1.0f / 256.0f) - mean1 * mean1, 0.0f);
            float inv1 = 1.0f / (sqrtf(var1 + LN_EPS) + LN_EPS);
            float hc0 = tanhf(s1c0 + g1c3 * ((tot0 - mean0) * inv0) + be1c3);
            float hc1 = tanhf(s1c1 + g1c3 * ((tot1 - mean1) * inv1) + be1c3);
            float z0 = sz[c2], z1 = sz[256 + c2];
            float h0 = sh[c2], h1 = sh[256 + c2];
            float hn0 = z0 * h0 + (1.0f - z0) * hc0;
            float hn1 = z1 * h1 + (1.0f - z1) * hc1;
            sh[c2]       = m0 ? hn0 : h0;
            sh[256 + c2] = m1 ? hn1 : h1;
        }
        __syncthreads();
    }

    if (half == 0) {
        out[(size_t)b0 * 512 + c2] = sh[c2];
        out[(size_t)b1 * 512 + c2] = sh[256 + c2];
    }
}

// ---------------- launch ---------------------------------------------------
extern "C" void kernel_launch(void* const* d_in, const int* in_sizes, int n_in,
                              void* d_out, int out_size) {
    const int* x           = (const int*)d_in[0];   // token ids (int32)
    // d_in[1] = bucket_size (constant 512, unused)
    const float* emb       = (const float*)d_in[2];
    const float* W         = (const float*)d_in[3];
    const float* Umat      = (const float*)d_in[4];
    const float* bias      = (const float*)d_in[5];
    const float* gammas    = (const float*)d_in[6];
    const float* betas     = (const float*)d_in[7];
    const float* kern      = (const float*)d_in[8];
    float* out             = (float*)d_out;

    float *xe, *s1p;
    cudaGetSymbolAddress((void**)&xe, g_xemb);
    cudaGetSymbolAddress((void**)&s1p, g_s1);

    // 1) embedding gather
    embed_kernel<<<TT * BB, 256>>>(x, emb);
    // 2) s1 = x_emb @ W + b  (M=32768, N=768, K=256), then LN in place
    gemm128<<<dim3(N3 / 128, TT * BB / 128), 256>>>(xe, W, bias, s1p,
                                                    N3, NU, 0);
    ln_kernel<<<TT * BB, 256>>>(gammas, betas);
    // 3) conv as ONE K=768 GEMM (M = 510*64 = 32640 rows) with fused max
    encinit_kernel<<<BB, 256>>>();
    gemm128<<<dim3(NU / 128, (510 * BB) / 128), 256>>>(xe, kern, nullptr,
                                                       nullptr, NU, 3 * NU, 1);
    decode_kernel<<<BB, 256>>>(out);
    // 4) recurrence (dominant, sequential)
    static const size_t rec_smem = REC_SMEM_FLOATS * sizeof(float);
    cudaFuncSetAttribute(rec_kernel, cudaFuncAttributeMaxDynamicSharedMemorySize,
                         (int)rec_smem);
    rec_kernel<<<32, 512, rec_smem>>>(x, Umat, s1p, gammas, betas, out);
}

// round 4
// speedup vs baseline: 1.8528x; 1.7841x over previous
#include <cuda_runtime.h>
#include <math.h>

// Problem constants (fixed shapes)
#define BB 64      // batch
#define TT 512     // time / bucket_size
#define NU 256     // units
#define N3 768     // 3*units
#define LN_EPS 1e-5f

typedef unsigned long long ull;
typedef unsigned int uint;

// ---------------- scratch (static device arrays; no runtime allocation) ----
__device__ float g_xemb[TT * BB * NU];   // [t][b][c]   33.5 MB
__device__ float g_s1[TT * BB * N3];     // [t][b][768] 100 MB (LN'd in place)
__device__ uint  g_enc[BB * NU];         // encoded running max for conv

// ---------------- small helpers -------------------------------------------
__device__ __forceinline__ uint enc_f(float v) {
    uint u = __float_as_uint(v);
    return ((int)u < 0) ? ~u : (u | 0x80000000u);
}
__device__ __forceinline__ float dec_f(uint e) {
    uint u = (e & 0x80000000u) ? (e ^ 0x80000000u) : ~e;
    return __uint_as_float(u);
}
__device__ __forceinline__ float hsig(float v) {
    return fminf(fmaxf(0.2f * v + 0.5f, 0.0f), 1.0f);
}
__device__ __forceinline__ float2 ull2f2(ull v) {
    float2 r;
    asm("mov.b64 {%0, %1}, %2;" : "=f"(r.x), "=f"(r.y) : "l"(v));
    return r;
}
__device__ __forceinline__ ull f22ull(float2 v) {
    ull r;
    asm("mov.b64 %0, {%1, %2};" : "=l"(r) : "f"(v.x), "f"(v.y));
    return r;
}
// packed fma: acc.{lo,hi} += hk.{lo,hi} * u
#define FMA2(acc, hk, uval) do {                                          \
    ull _pu;                                                              \
    asm("mov.b64 %0, {%1, %1};" : "=l"(_pu) : "f"(uval));                 \
    asm("fma.rn.f32x2 %0, %1, %2, %0;" : "+l"(acc) : "l"(hk), "l"(_pu));  \
} while (0)

__device__ __forceinline__ uint ctarank() {
    uint r; asm("mov.u32 %0, %%cluster_ctarank;" : "=r"(r)); return r;
}
__device__ __forceinline__ void st_cl_b64(void* laddr, uint r, ull v) {
    uint la = (uint)__cvta_generic_to_shared(laddr);
    asm volatile(
        "{ .reg .b32 ra; mapa.shared::cluster.u32 ra, %0, %1; "
        "st.shared::cluster.b64 [ra], %2; }"
        :: "r"(la), "r"(r), "l"(v) : "memory");
}
#define CLUSTER_SYNC() do {                                        \
    asm volatile("barrier.cluster.arrive.aligned;" ::: "memory");  \
    asm volatile("barrier.cluster.wait.aligned;" ::: "memory");    \
} while (0)

// ---------------- embedding gather ----------------------------------------
__global__ void embed_kernel(const int* __restrict__ x,
                             const float* __restrict__ emb) {
    int idx = blockIdx.x * 256 + threadIdx.x;
    int c = idx & 255;
    int b = (idx >> 8) & 63;
    int t = idx >> 14;
    int row = x[(size_t)b * TT + t];
    g_xemb[idx] = emb[(size_t)row * NU + c];
}

__global__ void encinit_kernel() {
    g_enc[blockIdx.x * 256 + threadIdx.x] = enc_f(-INFINITY);
}
__global__ void decode_kernel(float* __restrict__ out) {
    int f = threadIdx.x;           // 256
    int b = blockIdx.x;            // 64
    out[(size_t)b * 512 + 256 + f] = dec_f(g_enc[b * 256 + f]);
}

// ---------------- 128x128 fp32 GEMM with f32x2 packed FMAs -----------------
#define SP_A 132
__global__ void __launch_bounds__(256, 2)
gemm128(const float* __restrict__ A, const float* __restrict__ B,
        const float* __restrict__ bias, float* __restrict__ C,
        int N, int K, int domax) {
    __shared__ float As[2][8 * SP_A];
    __shared__ float Bs[2][8 * 128];

    int tid = threadIdx.x;
    int tx = tid & 15, ty = tid >> 4;
    int r0 = blockIdx.y * 128, c0 = blockIdx.x * 128;

    int am = tid >> 1, akq = (tid & 1) * 4;
    int bk = tid >> 5, bn = (tid & 31) * 4;

    ull acc[8][4];
    #pragma unroll
    for (int i = 0; i < 8; i++)
        #pragma unroll
        for (int j = 0; j < 4; j++) acc[i][j] = 0ull;

    const float* Arow = A + (size_t)(r0 + am) * 256;

    int k = akq;
    float4 aR = *(const float4*)&Arow[((k >> 8) << 14) + (k & 255)];
    float4 bR = *(const float4*)&B[(size_t)bk * N + c0 + bn];
    {
        float* as = As[0];
        as[(akq + 0) * SP_A + am] = aR.x;
        as[(akq + 1) * SP_A + am] = aR.y;
        as[(akq + 2) * SP_A + am] = aR.z;
        as[(akq + 3) * SP_A + am] = aR.w;
        *(float4*)&Bs[0][bk * 128 + bn] = bR;
    }
    __syncthreads();

    int buf = 0;
    for (int k0 = 0; k0 < K; k0 += 8) {
        bool more = (k0 + 8) < K;
        if (more) {
            k = k0 + 8 + akq;
            aR = *(const float4*)&Arow[((k >> 8) << 14) + (k & 255)];
            bR = *(const float4*)&B[(size_t)(k0 + 8 + bk) * N + c0 + bn];
        }
        const float* as = As[buf];
        const float* bs = Bs[buf];
        #pragma unroll
        for (int kk = 0; kk < 8; kk++) {
            float4 a0 = *(const float4*)&as[kk * SP_A + ty * 8];
            float4 a1 = *(const float4*)&as[kk * SP_A + ty * 8 + 4];
            float4 b0 = *(const float4*)&bs[kk * 128 + tx * 8];
            float4 b1 = *(const float4*)&bs[kk * 128 + tx * 8 + 4];
            ull pb[4];
            pb[0] = f22ull(make_float2(b0.x, b0.y));
            pb[1] = f22ull(make_float2(b0.z, b0.w));
            pb[2] = f22ull(make_float2(b1.x, b1.y));
            pb[3] = f22ull(make_float2(b1.z, b1.w));
            float av[8] = {a0.x, a0.y, a0.z, a0.w, a1.x, a1.y, a1.z, a1.w};
            #pragma unroll
            for (int i = 0; i < 8; i++) {
                ull pa;
                asm("mov.b64 %0, {%1, %1};" : "=l"(pa) : "f"(av[i]));
                #pragma unroll
                for (int j = 0; j < 4; j++)
                    asm("fma.rn.f32x2 %0, %1, %2, %0;"
                        : "+l"(acc[i][j]) : "l"(pa), "l"(pb[j]));
            }
        }
        if (more) {
            float* asn = As[buf ^ 1];
            asn[(akq + 0) * SP_A + am] = aR.x;
            asn[(akq + 1) * SP_A + am] = aR.y;
            asn[(akq + 2) * SP_A + am] = aR.z;
            asn[(akq + 3) * SP_A + am] = aR.w;
            *(float4*)&Bs[buf ^ 1][bk * 128 + bn] = bR;
        }
        __syncthreads();
        buf ^= 1;
    }

    float bv[8];
    if (bias) {
        #pragma unroll
        for (int j = 0; j < 8; j++) bv[j] = bias[c0 + tx * 8 + j];
    }
    #pragma unroll
    for (int i = 0; i < 8; i++) {
        int row = r0 + ty * 8 + i;
        float v[8];
        #pragma unroll
        for (int j = 0; j < 4; j++) {
            float2 f = ull2f2(acc[i][j]);
            v[2 * j] = f.x; v[2 * j + 1] = f.y;
        }
        if (bias) {
            #pragma unroll
            for (int j = 0; j < 8; j++) v[j] += bv[j];
        }
        if (C) {
            float4 s0 = make_float4(v[0], v[1], v[2], v[3]);
            float4 s1 = make_float4(v[4], v[5], v[6], v[7]);
            *(float4*)&C[(size_t)row * N + c0 + tx * 8] = s0;
            *(float4*)&C[(size_t)row * N + c0 + tx * 8 + 4] = s1;
        }
        if (domax) {
            int b = row & 63;
            #pragma unroll
            for (int j = 0; j < 8; j++)
                atomicMax(&g_enc[b * 256 + c0 + tx * 8 + j], enc_f(v[j]));
        }
    }
}

// ---------------- row LayerNorm over 768 cols, in place on g_s1 ------------
__global__ void ln_kernel(const float* __restrict__ gam,
                          const float* __restrict__ bet) {
    int row = blockIdx.x;
    float* p = g_s1 + (size_t)row * N3;
    int tid = threadIdx.x;
    float v0 = p[tid], v1 = p[tid + 256], v2 = p[tid + 512];
    float s = v0 + v1 + v2;
    float q = v0 * v0 + v1 * v1 + v2 * v2;
    __shared__ float rs[8], rq[8];
    __shared__ float tot[2];
    int lane = tid & 31, w = tid >> 5;
    #pragma unroll
    for (int o = 16; o; o >>= 1) {
        s += __shfl_down_sync(0xffffffffu, s, o);
        q += __shfl_down_sync(0xffffffffu, q, o);
    }
    if (!lane) { rs[w] = s; rq[w] = q; }
    __syncthreads();
    if (tid == 0) {
        float S = 0, Q = 0;
        for (int i = 0; i < 8; i++) { S += rs[i]; Q += rq[i]; }
        tot[0] = S; tot[1] = Q;
    }
    __syncthreads();
    float mean = tot[0] * (1.0f / 768.0f);
    float var = fmaxf(tot[1] * (1.0f / 768.0f) - mean * mean, 0.0f);
    float inv = 1.0f / (sqrtf(var + LN_EPS) + LN_EPS);
    p[tid]       = gam[tid]       * ((v0 - mean) * inv) + bet[tid];
    p[tid + 256] = gam[tid + 256] * ((v1 - mean) * inv) + bet[tid + 256];
    p[tid + 512] = gam[tid + 512] * ((v2 - mean) * inv) + bet[tid + 512];
}

// =============== recurrence: 32 clusters x 4 CTAs, U fully in SMEM =========
// cluster c handles batch rows 2c, 2c+1 (packed in f32x2 lanes).
// CTA rank r owns units u in [64r, 64r+64): columns {u, 256+u, 512+u}.
// SMEM U layout: col-major slice, local col 0..63 = z-cols, 64..127 = r-cols,
// 128..191 = hc-cols; stride 260 floats (16B-aligned, conflict-benign).
#define USTRIDE 260
#define REC_SMEM_FLOATS (192 * USTRIDE + 512 + 512 + 128 + 384 + 16 + 16 + 16)

__global__ void __launch_bounds__(256, 1) __cluster_dims__(4, 1, 1)
rec_kernel(const int* __restrict__ x, const float* __restrict__ Umat,
           const float* __restrict__ s1, const float* __restrict__ gammas,
           const float* __restrict__ betas, float* __restrict__ out) {
    extern __shared__ float sm[];
    float*  sU   = sm;                               // 192*260
    float2* h2   = (float2*)(sm + 192 * USTRIDE);    // 256
    float2* rh2  = h2 + 256;                         // 256
    float2* z2   = rh2 + 256;                        // 64
    float2* cbuf = z2 + 64;                          // 192
    float2* wsl  = cbuf + 192;                       // 8 (warp slots)
    float2* pA   = wsl + 8;                          // 8 (rank sums / sqs)
    float2* pB   = pA + 8;                           // 8

    int tid  = threadIdx.x;
    uint rank = ctarank();
    int cid  = blockIdx.x >> 2;
    int b0   = cid * 2, b1 = b0 + 1;
    int lane = tid & 31, wid = tid >> 5;

    // ---- one-time: load this CTA's 192 U columns into smem ----
    for (int i = tid; i < 192 * 256; i += 256) {
        int k = i / 192;
        int c = i - k * 192;
        int seg = c >> 6;                        // 0:z 1:r 2:hc
        int gcol = seg * 256 + (int)rank * 64 + (c & 63);
        sU[c * USTRIDE + k] = Umat[(size_t)k * N3 + gcol];
    }
    h2[tid] = make_float2(0.0f, 0.0f);
    __syncthreads();

    // per-thread constants
    int colA = tid & 127;                        // phase-A col (z or r)
    int khalf = tid >> 7;                        // 0/1
    int gA = (colA < 64) ? ((int)rank * 64 + colA)
                         : (256 + (int)rank * 64 + (colA - 64));
    float g1a = gammas[N3 + gA], be1a = betas[N3 + gA];
    int u = (int)rank * 64 + (tid & 63);         // owned unit (valid tid<64)
    float g1b = gammas[N3 + 512 + u], be1b = betas[N3 + 512 + u];
    int uB = tid & 63, kq = tid >> 6;            // phase-B mapping

    const float* ucA = &sU[colA * USTRIDE + khalf * 128];
    const ull*   hpA = (const ull*)h2 + khalf * 128;
    const float* ucB = &sU[(128 + uB) * USTRIDE + kq * 64];
    const ull*   rpB = (const ull*)rh2 + kq * 64;

    CLUSTER_SYNC();   // peers' smem initialized before any remote write

    for (int t = 0; t < TT; t++) {
        // prefetch s1 / masks (consumed late; overlaps matmul)
        const float* s1r0 = s1 + ((size_t)t * 64 + b0) * N3;
        const float* s1r1 = s1r0 + N3;
        float s1a0 = 0, s1a1 = 0, s1c0 = 0, s1c1 = 0;
        int m0 = 1, m1 = 1;
        if (tid < 128) { s1a0 = s1r0[gA]; s1a1 = s1r1[gA]; }
        if (tid < 64) {
            s1c0 = s1r0[512 + u]; s1c1 = s1r1[512 + u];
            m0 = x[(size_t)b0 * TT + t]; m1 = x[(size_t)b1 * TT + t];
        }

        // ---- phase A: partial h @ U[:, col], k-half per thread ----
        ull acc = 0ull;
        #pragma unroll 8
        for (int k = 0; k < 128; k += 4) {
            float4 uv = *(const float4*)&ucA[k];
            ulonglong2 ha = *(const ulonglong2*)(hpA + k);
            ulonglong2 hb = *(const ulonglong2*)(hpA + k + 2);
            FMA2(acc, ha.x, uv.x); FMA2(acc, ha.y, uv.y);
            FMA2(acc, hb.x, uv.z); FMA2(acc, hb.y, uv.w);
        }
        if (tid >= 128) cbuf[tid - 128] = ull2f2(acc);
        __syncthreads();

        float2 sval = make_float2(0.0f, 0.0f);
        if (tid < 128) {
            float2 mine = ull2f2(acc), oth = cbuf[tid];
            sval.x = mine.x + oth.x; sval.y = mine.y + oth.y;
            float p0 = sval.x, p1 = sval.y;
            float q0 = p0 * p0, q1 = p1 * p1;
            #pragma unroll
            for (int o = 16; o; o >>= 1) {
                p0 += __shfl_down_sync(0xffffffffu, p0, o);
                p1 += __shfl_down_sync(0xffffffffu, p1, o);
                q0 += __shfl_down_sync(0xffffffffu, q0, o);
                q1 += __shfl_down_sync(0xffffffffu, q1, o);
            }
            if (!lane) { wsl[wid] = make_float2(p0, p1); wsl[4 + wid] = make_float2(q0, q1); }
        }
        __syncthreads();
        if (tid == 0) {
            float2 S = make_float2(0, 0), Q = make_float2(0, 0);
            #pragma unroll
            for (int w = 0; w < 4; w++) {
                S.x += wsl[w].x; S.y += wsl[w].y;
                Q.x += wsl[4 + w].x; Q.y += wsl[4 + w].y;
            }
            #pragma unroll
            for (uint r = 0; r < 4; r++) {
                st_cl_b64(&pA[rank], r, f22ull(S));
                st_cl_b64(&pA[4 + rank], r, f22ull(Q));
            }
        }
        CLUSTER_SYNC();   // S1: LN-A partials visible everywhere

        // ---- gate ----
        if (tid < 128) {
            float2 S = make_float2(0, 0), Q = make_float2(0, 0);
            #pragma unroll
            for (int r = 0; r < 4; r++) {
                S.x += pA[r].x; S.y += pA[r].y;
                Q.x += pA[4 + r].x; Q.y += pA[4 + r].y;
            }
            float mean0 = S.x * (1.0f / 512.0f), mean1 = S.y * (1.0f / 512.0f);
            float var0 = fmaxf(Q.x * (1.0f / 512.0f) - mean0 * mean0, 0.0f);
            float var1 = fmaxf(Q.y * (1.0f / 512.0f) - mean1 * mean1, 0.0f);
            float inv0 = 1.0f / (sqrtf(var0 + LN_EPS) + LN_EPS);
            float inv1 = 1.0f / (sqrtf(var1 + LN_EPS) + LN_EPS);
            float sv0 = hsig(s1a0 + g1a * ((sval.x - mean0) * inv0) + be1a);
            float sv1 = hsig(s1a1 + g1a * ((sval.y - mean1) * inv1) + be1a);
            if (tid < 64) {
                z2[tid] = make_float2(sv0, sv1);
            } else {
                int uu = (int)rank * 64 + tid - 64;
                float2 h = h2[uu];
                float2 rh = make_float2(sv0 * h.x, sv1 * h.y);
                ull pv = f22ull(rh);
                #pragma unroll
                for (uint r = 0; r < 4; r++) st_cl_b64(&rh2[uu], r, pv);
            }
        }
        CLUSTER_SYNC();   // S2: rh visible everywhere

        // ---- phase B: partial (r*h) @ U[:, 512+col], k-quarter per thread --
        ull accB = 0ull;
        #pragma unroll 8
        for (int k = 0; k < 64; k += 4) {
            float4 uv = *(const float4*)&ucB[k];
            ulonglong2 ha = *(const ulonglong2*)(rpB + k);
            ulonglong2 hb = *(const ulonglong2*)(rpB + k + 2);
            FMA2(accB, ha.x, uv.x); FMA2(accB, ha.y, uv.y);
            FMA2(accB, hb.x, uv.z); FMA2(accB, hb.y, uv.w);
        }
        if (tid >= 64) cbuf[tid - 64] = ull2f2(accB);
        __syncthreads();

        float2 sB = make_float2(0.0f, 0.0f);
        if (tid < 64) {
            float2 mine = ull2f2(accB);
            float2 o1 = cbuf[tid], o2 = cbuf[64 + tid], o3 = cbuf[128 + tid];
            sB.x = mine.x + o1.x + o2.x + o3.x;
            sB.y = mine.y + o1.y + o2.y + o3.y;
            float p0 = sB.x, p1 = sB.y, q0 = p0 * p0, q1 = p1 * p1;
            #pragma unroll
            for (int o = 16; o; o >>= 1) {
                p0 += __shfl_down_sync(0xffffffffu, p0, o);
                p1 += __shfl_down_sync(0xffffffffu, p1, o);
                q0 += __shfl_down_sync(0xffffffffu, q0, o);
                q1 += __shfl_down_sync(0xffffffffu, q1, o);
            }
            if (!lane) { wsl[wid] = make_float2(p0, p1); wsl[4 + wid] = make_float2(q0, q1); }
        }
        __syncthreads();
        if (tid == 0) {
            float2 S = make_float2(wsl[0].x + wsl[1].x, wsl[0].y + wsl[1].y);
            float2 Q = make_float2(wsl[4].x + wsl[5].x, wsl[4].y + wsl[5].y);
            #pragma unroll
            for (uint r = 0; r < 4; r++) {
                st_cl_b64(&pB[rank], r, f22ull(S));
                st_cl_b64(&pB[4 + rank], r, f22ull(Q));
            }
        }
        CLUSTER_SYNC();   // S3: LN-B partials visible everywhere

        // ---- phase C: hc, gated masked h update, broadcast h ----
        if (tid < 64) {
            float2 S = make_float2(0, 0), Q = make_float2(0, 0);
            #pragma unroll
            for (int r = 0; r < 4; r++) {
                S.x += pB[r].x; S.y += pB[r].y;
                Q.x += pB[4 + r].x; Q.y += pB[4 + r].y;
            }
            float mean0 = S.x * (1.0f / 256.0f), mean1 = S.y * (1.0f / 256.0f);
            float var0 = fmaxf(Q.x * (1.0f / 256.0f) - mean0 * mean0, 0.0f);
            float var1 = fmaxf(Q.y * (1.0f / 256.0f) - mean1 * mean1, 0.0f);
            float inv0 = 1.0f / (sqrtf(var0 + LN_EPS) + LN_EPS);
            float inv1 = 1.0f / (sqrtf(var1 + LN_EPS) + LN_EPS);
            float hc0 = tanhf(s1c0 + g1b * ((sB.x - mean0) * inv0) + be1b);
            float hc1 = tanhf(s1c1 + g1b * ((sB.y - mean1) * inv1) + be1b);
            float2 z = z2[tid];
            float2 h = h2[u];
            float hn0 = z.x * h.x + (1.0f - z.x) * hc0;
            float hn1 = z.y * h.y + (1.0f - z.y) * hc1;
            float2 hn = make_float2(m0 ? hn0 : h.x, m1 ? hn1 : h.y);
            ull pv = f22ull(hn);
            #pragma unroll
            for (uint r = 0; r < 4; r++) st_cl_b64(&h2[u], r, pv);
        }
        CLUSTER_SYNC();   // S4: h visible for next step
    }

    if (tid < 64) {
        float2 h = h2[u];
        out[(size_t)b0 * 512 + u] = h.x;
        out[(size_t)b1 * 512 + u] = h.y;
    }
}

// ---------------- launch ---------------------------------------------------
extern "C" void kernel_launch(void* const* d_in, const int* in_sizes, int n_in,
                              void* d_out, int out_size) {
    const int* x           = (const int*)d_in[0];   // token ids (int32)
    const float* emb       = (const float*)d_in[2];
    const float* W         = (const float*)d_in[3];
    const float* Umat      = (const float*)d_in[4];
    const float* bias      = (const float*)d_in[5];
    const float* gammas    = (const float*)d_in[6];
    const float* betas     = (const float*)d_in[7];
    const float* kern      = (const float*)d_in[8];
    float* out             = (float*)d_out;

    float *xe, *s1p;
    cudaGetSymbolAddress((void**)&xe, g_xemb);
    cudaGetSymbolAddress((void**)&s1p, g_s1);

    // 1) embedding gather
    embed_kernel<<<TT * BB, 256>>>(x, emb);
    // 2) s1 = x_emb @ W + b  (M=32768, N=768, K=256), then LN in place
    gemm128<<<dim3(N3 / 128, TT * BB / 128), 256>>>(xe, W, bias, s1p,
                                                    N3, NU, 0);
    ln_kernel<<<TT * BB, 256>>>(gammas, betas);
    // 3) conv as ONE K=768 GEMM with fused max
    encinit_kernel<<<BB, 256>>>();
    gemm128<<<dim3(NU / 128, (510 * BB) / 128), 256>>>(xe, kern, nullptr,
                                                       nullptr, NU, 3 * NU, 1);
    decode_kernel<<<BB, 256>>>(out);
    // 4) recurrence: cluster-parallel, U fully SMEM-resident
    static const size_t rec_smem = REC_SMEM_FLOATS * sizeof(float);
    cudaFuncSetAttribute(rec_kernel, cudaFuncAttributeMaxDynamicSharedMemorySize,
                         (int)rec_smem);
    rec_kernel<<<128, 256, rec_smem>>>(x, Umat, s1p, gammas, betas, out);
}

// round 5
// speedup vs baseline: 2.2415x; 1.2098x over previous
#include <cuda_runtime.h>
#include <math.h>

// Problem constants (fixed shapes)
#define BB 64      // batch
#define TT 512     // time / bucket_size
#define NU 256     // units
#define N3 768     // 3*units
#define LN_EPS 1e-5f

typedef unsigned long long ull;
typedef unsigned int uint;

// ---------------- scratch (static device arrays; no runtime allocation) ----
__device__ float g_xemb[TT * BB * NU];   // [t][b][c]   33.5 MB
__device__ float g_s1[TT * BB * N3];     // [t][b][768] 100 MB (LN'd in place)
__device__ uint  g_enc[BB * NU];         // encoded running max for conv

// ---------------- small helpers -------------------------------------------
__device__ __forceinline__ uint enc_f(float v) {
    uint u = __float_as_uint(v);
    return ((int)u < 0) ? ~u : (u | 0x80000000u);
}
__device__ __forceinline__ float dec_f(uint e) {
    uint u = (e & 0x80000000u) ? (e ^ 0x80000000u) : ~e;
    return __uint_as_float(u);
}
__device__ __forceinline__ float hsig(float v) {
    return fminf(fmaxf(0.2f * v + 0.5f, 0.0f), 1.0f);
}
__device__ __forceinline__ float2 ull2f2(ull v) {
    float2 r;
    asm("mov.b64 {%0, %1}, %2;" : "=f"(r.x), "=f"(r.y) : "l"(v));
    return r;
}
__device__ __forceinline__ ull f22ull(float2 v) {
    ull r;
    asm("mov.b64 %0, {%1, %2};" : "=l"(r) : "f"(v.x), "f"(v.y));
    return r;
}
// packed fma: acc.{lo,hi} += hk.{lo,hi} * u
#define FMA2(acc, hk, uval) do {                                          \
    ull _pu;                                                              \
    asm("mov.b64 %0, {%1, %1};" : "=l"(_pu) : "f"(uval));                 \
    asm("fma.rn.f32x2 %0, %1, %2, %0;" : "+l"(acc) : "l"(hk), "l"(_pu));  \
} while (0)

__device__ __forceinline__ uint ctarank() {
    uint r; asm("mov.u32 %0, %%cluster_ctarank;" : "=r"(r)); return r;
}
__device__ __forceinline__ void st_cl_b64(void* laddr, uint r, ull v) {
    uint la = (uint)__cvta_generic_to_shared(laddr);
    asm volatile(
        "{ .reg .b32 ra; mapa.shared::cluster.u32 ra, %0, %1; "
        "st.shared::cluster.b64 [ra], %2; }"
        :: "r"(la), "r"(r), "l"(v) : "memory");
}
#define CLUSTER_SYNC() do {                                        \
    asm volatile("barrier.cluster.arrive.aligned;" ::: "memory");  \
    asm volatile("barrier.cluster.wait.aligned;" ::: "memory");    \
} while (0)

// ---------------- embedding gather ----------------------------------------
__global__ void embed_kernel(const int* __restrict__ x,
                             const float* __restrict__ emb) {
    int idx = blockIdx.x * 256 + threadIdx.x;
    int c = idx & 255;
    int b = (idx >> 8) & 63;
    int t = idx >> 14;
    int row = x[(size_t)b * TT + t];
    g_xemb[idx] = emb[(size_t)row * NU + c];
}

__global__ void encinit_kernel() {
    g_enc[blockIdx.x * 256 + threadIdx.x] = enc_f(-INFINITY);
}
__global__ void decode_kernel(float* __restrict__ out) {
    int f = threadIdx.x;           // 256
    int b = blockIdx.x;            // 64
    out[(size_t)b * 512 + 256 + f] = dec_f(g_enc[b * 256 + f]);
}

// ---------------- 128x128 fp32 GEMM with f32x2 packed FMAs -----------------
#define SP_A 132
__global__ void __launch_bounds__(256, 2)
gemm128(const float* __restrict__ A, const float* __restrict__ B,
        const float* __restrict__ bias, float* __restrict__ C,
        int N, int K, int domax) {
    __shared__ float As[2][8 * SP_A];
    __shared__ float Bs[2][8 * 128];

    int tid = threadIdx.x;
    int tx = tid & 15, ty = tid >> 4;
    int r0 = blockIdx.y * 128, c0 = blockIdx.x * 128;

    int am = tid >> 1, akq = (tid & 1) * 4;
    int bk = tid >> 5, bn = (tid & 31) * 4;

    ull acc[8][4];
    #pragma unroll
    for (int i = 0; i < 8; i++)
        #pragma unroll
        for (int j = 0; j < 4; j++) acc[i][j] = 0ull;

    const float* Arow = A + (size_t)(r0 + am) * 256;

    int k = akq;
    float4 aR = *(const float4*)&Arow[((k >> 8) << 14) + (k & 255)];
    float4 bR = *(const float4*)&B[(size_t)bk * N + c0 + bn];
    {
        float* as = As[0];
        as[(akq + 0) * SP_A + am] = aR.x;
        as[(akq + 1) * SP_A + am] = aR.y;
        as[(akq + 2) * SP_A + am] = aR.z;
        as[(akq + 3) * SP_A + am] = aR.w;
        *(float4*)&Bs[0][bk * 128 + bn] = bR;
    }
    __syncthreads();

    int buf = 0;
    for (int k0 = 0; k0 < K; k0 += 8) {
        bool more = (k0 + 8) < K;
        if (more) {
            k = k0 + 8 + akq;
            aR = *(const float4*)&Arow[((k >> 8) << 14) + (k & 255)];
            bR = *(const float4*)&B[(size_t)(k0 + 8 + bk) * N + c0 + bn];
        }
        const float* as = As[buf];
        const float* bs = Bs[buf];
        #pragma unroll
        for (int kk = 0; kk < 8; kk++) {
            float4 a0 = *(const float4*)&as[kk * SP_A + ty * 8];
            float4 a1 = *(const float4*)&as[kk * SP_A + ty * 8 + 4];
            float4 b0 = *(const float4*)&bs[kk * 128 + tx * 8];
            float4 b1 = *(const float4*)&bs[kk * 128 + tx * 8 + 4];
            ull pb[4];
            pb[0] = f22ull(make_float2(b0.x, b0.y));
            pb[1] = f22ull(make_float2(b0.z, b0.w));
            pb[2] = f22ull(make_float2(b1.x, b1.y));
            pb[3] = f22ull(make_float2(b1.z, b1.w));
            float av[8] = {a0.x, a0.y, a0.z, a0.w, a1.x, a1.y, a1.z, a1.w};
            #pragma unroll
            for (int i = 0; i < 8; i++) {
                ull pa;
                asm("mov.b64 %0, {%1, %1};" : "=l"(pa) : "f"(av[i]));
                #pragma unroll
                for (int j = 0; j < 4; j++)
                    asm("fma.rn.f32x2 %0, %1, %2, %0;"
                        : "+l"(acc[i][j]) : "l"(pa), "l"(pb[j]));
            }
        }
        if (more) {
            float* asn = As[buf ^ 1];
            asn[(akq + 0) * SP_A + am] = aR.x;
            asn[(akq + 1) * SP_A + am] = aR.y;
            asn[(akq + 2) * SP_A + am] = aR.z;
            asn[(akq + 3) * SP_A + am] = aR.w;
            *(float4*)&Bs[buf ^ 1][bk * 128 + bn] = bR;
        }
        __syncthreads();
        buf ^= 1;
    }

    float bv[8];
    if (bias) {
        #pragma unroll
        for (int j = 0; j < 8; j++) bv[j] = bias[c0 + tx * 8 + j];
    }
    #pragma unroll
    for (int i = 0; i < 8; i++) {
        int row = r0 + ty * 8 + i;
        float v[8];
        #pragma unroll
        for (int j = 0; j < 4; j++) {
            float2 f = ull2f2(acc[i][j]);
            v[2 * j] = f.x; v[2 * j + 1] = f.y;
        }
        if (bias) {
            #pragma unroll
            for (int j = 0; j < 8; j++) v[j] += bv[j];
        }
        if (C) {
            float4 s0 = make_float4(v[0], v[1], v[2], v[3]);
            float4 s1 = make_float4(v[4], v[5], v[6], v[7]);
            *(float4*)&C[(size_t)row * N + c0 + tx * 8] = s0;
            *(float4*)&C[(size_t)row * N + c0 + tx * 8 + 4] = s1;
        }
        if (domax) {
            int b = row & 63;
            #pragma unroll
            for (int j = 0; j < 8; j++)
                atomicMax(&g_enc[b * 256 + c0 + tx * 8 + j], enc_f(v[j]));
        }
    }
}

// ---------------- row LayerNorm over 768 cols, in place on g_s1 ------------
__global__ void ln_kernel(const float* __restrict__ gam,
                          const float* __restrict__ bet) {
    int row = blockIdx.x;
    float* p = g_s1 + (size_t)row * N3;
    int tid = threadIdx.x;
    float v0 = p[tid], v1 = p[tid + 256], v2 = p[tid + 512];
    float s = v0 + v1 + v2;
    float q = v0 * v0 + v1 * v1 + v2 * v2;
    __shared__ float rs[8], rq[8];
    __shared__ float tot[2];
    int lane = tid & 31, w = tid >> 5;
    #pragma unroll
    for (int o = 16; o; o >>= 1) {
        s += __shfl_down_sync(0xffffffffu, s, o);
        q += __shfl_down_sync(0xffffffffu, q, o);
    }
    if (!lane) { rs[w] = s; rq[w] = q; }
    __syncthreads();
    if (tid == 0) {
        float S = 0, Q = 0;
        for (int i = 0; i < 8; i++) { S += rs[i]; Q += rq[i]; }
        tot[0] = S; tot[1] = Q;
    }
    __syncthreads();
    float mean = tot[0] * (1.0f / 768.0f);
    float var = fmaxf(tot[1] * (1.0f / 768.0f) - mean * mean, 0.0f);
    float inv = 1.0f / (sqrtf(var + LN_EPS) + LN_EPS);
    p[tid]       = gam[tid]       * ((v0 - mean) * inv) + bet[tid];
    p[tid + 256] = gam[tid + 256] * ((v1 - mean) * inv) + bet[tid + 256];
    p[tid + 512] = gam[tid + 512] * ((v2 - mean) * inv) + bet[tid + 512];
}

// =============== recurrence: 32 clusters x 4 CTAs, U in REGISTERS ==========
// cluster c handles batch rows 2c, 2c+1 (packed in f32x2 lanes).
// Phase A: thread (colA = tid&127, khalf = tid>>7) owns U[:,gA] k-half (128 regs).
//   CTA rank r covers z cols [64r,64r+64) and r cols [256+64r, 256+64r+64).
// Phase B: thread (uB = tid&63, kq = tid>>6) owns U[:,512+gB] k-quarter (64 regs).
// Phase C computed redundantly by ALL CTAs (z and sB broadcast) -> no h sync.
__global__ void __launch_bounds__(256, 1) __cluster_dims__(4, 1, 1)
rec_kernel(const int* __restrict__ x, const float* __restrict__ Umat,
           const float* __restrict__ s1, const float* __restrict__ gammas,
           const float* __restrict__ betas, float* __restrict__ out) {
    __shared__ __align__(16) float2 h2[256];    // h, local authoritative copy
    __shared__ __align__(16) float2 rh2[256];   // r*h (cluster-broadcast)
    __shared__ __align__(16) float2 z2g[256];   // z gates (cluster-broadcast)
    __shared__ __align__(16) float2 sBg[256];   // hc presums (cluster-broadcast)
    __shared__ __align__(16) float2 cbuf[192];  // intra-CTA partial exchange
    __shared__ float2 wsl[8];                   // warp reduction slots
    __shared__ float2 pA[8];                    // LN-A partials per rank (S,Q)
    __shared__ float2 pB[8];                    // LN-B partials per rank (S,Q)

    int tid  = threadIdx.x;
    uint rank = ctarank();
    int cid  = blockIdx.x >> 2;
    int b0   = cid * 2, b1 = b0 + 1;
    int lane = tid & 31, wid = tid >> 5;

    int colA  = tid & 127;
    int khalf = tid >> 7;
    int gA = (colA < 64) ? ((int)rank * 64 + colA)
                         : (256 + (int)rank * 64 + (colA - 64));
    float g1a = gammas[N3 + gA], be1a = betas[N3 + gA];
    int uC = tid;                                 // phase-C unit (0..255)
    float g1c = gammas[N3 + 512 + uC], be1c = betas[N3 + 512 + uC];
    int uB = tid & 63, kq = tid >> 6;
    int gB = (int)rank * 64 + uB;

    // ---- one-time: U slices into registers ----
    float UA[128];
    #pragma unroll
    for (int k = 0; k < 128; k++)
        UA[k] = Umat[(size_t)(khalf * 128 + k) * N3 + gA];
    float UB[64];
    #pragma unroll
    for (int j = 0; j < 64; j++)
        UB[j] = Umat[(size_t)(kq * 64 + j) * N3 + 512 + gB];

    h2[tid] = make_float2(0.0f, 0.0f);
    __syncthreads();
    CLUSTER_SYNC();

    for (int t = 0; t < TT; t++) {
        // prefetch s1 / masks (consumed late)
        const float* s1r0 = s1 + ((size_t)t * 64 + b0) * N3;
        const float* s1r1 = s1r0 + N3;
        float s1a0 = 0.0f, s1a1 = 0.0f;
        if (tid < 128) { s1a0 = s1r0[gA]; s1a1 = s1r1[gA]; }
        float s1c0 = s1r0[512 + uC], s1c1 = s1r1[512 + uC];
        int m0 = x[(size_t)b0 * TT + t], m1 = x[(size_t)b1 * TT + t];

        // ---- phase A: h @ U[:, gA] over k-half (U in regs, h broadcast) --
        const ull* hp = (const ull*)h2 + khalf * 128;
        ull a0 = 0, a1 = 0, a2 = 0, a3 = 0;
        #pragma unroll
        for (int k = 0; k < 128; k += 4) {
            ulonglong2 ha = *(const ulonglong2*)(hp + k);
            ulonglong2 hb = *(const ulonglong2*)(hp + k + 2);
            FMA2(a0, ha.x, UA[k]);     FMA2(a1, ha.y, UA[k + 1]);
            FMA2(a2, hb.x, UA[k + 2]); FMA2(a3, hb.y, UA[k + 3]);
        }
        float2 f0 = ull2f2(a0), f1 = ull2f2(a1);
        float2 f2v = ull2f2(a2), f3 = ull2f2(a3);
        float2 accA = make_float2((f0.x + f1.x) + (f2v.x + f3.x),
                                  (f0.y + f1.y) + (f2v.y + f3.y));
        if (tid >= 128) cbuf[tid - 128] = accA;
        __syncthreads();

        float2 sval = make_float2(0.0f, 0.0f);
        if (tid < 128) {
            float2 oth = cbuf[tid];
            sval.x = accA.x + oth.x; sval.y = accA.y + oth.y;
            float p0 = sval.x, p1 = sval.y;
            float q0 = p0 * p0, q1 = p1 * p1;
            #pragma unroll
            for (int o = 16; o; o >>= 1) {
                p0 += __shfl_down_sync(0xffffffffu, p0, o);
                p1 += __shfl_down_sync(0xffffffffu, p1, o);
                q0 += __shfl_down_sync(0xffffffffu, q0, o);
                q1 += __shfl_down_sync(0xffffffffu, q1, o);
            }
            if (!lane) { wsl[wid] = make_float2(p0, p1);
                         wsl[4 + wid] = make_float2(q0, q1); }
        }
        __syncthreads();
        if (tid == 0) {
            float2 S = make_float2(0, 0), Q = make_float2(0, 0);
            #pragma unroll
            for (int w = 0; w < 4; w++) {
                S.x += wsl[w].x; S.y += wsl[w].y;
                Q.x += wsl[4 + w].x; Q.y += wsl[4 + w].y;
            }
            #pragma unroll
            for (uint r = 0; r < 4; r++) {
                st_cl_b64(&pA[rank], r, f22ull(S));
                st_cl_b64(&pA[4 + rank], r, f22ull(Q));
            }
        }
        CLUSTER_SYNC();   // S1: LN-A partials visible everywhere

        // ---- gate: z broadcast, rh broadcast ----
        if (tid < 128) {
            float2 S = make_float2(0, 0), Q = make_float2(0, 0);
            #pragma unroll
            for (int r = 0; r < 4; r++) {
                S.x += pA[r].x; S.y += pA[r].y;
                Q.x += pA[4 + r].x; Q.y += pA[4 + r].y;
            }
            float mean0 = S.x * (1.0f / 512.0f), mean1 = S.y * (1.0f / 512.0f);
            float var0 = fmaxf(Q.x * (1.0f / 512.0f) - mean0 * mean0, 0.0f);
            float var1 = fmaxf(Q.y * (1.0f / 512.0f) - mean1 * mean1, 0.0f);
            float inv0 = 1.0f / (sqrtf(var0 + LN_EPS) + LN_EPS);
            float inv1 = 1.0f / (sqrtf(var1 + LN_EPS) + LN_EPS);
            float sv0 = hsig(s1a0 + g1a * ((sval.x - mean0) * inv0) + be1a);
            float sv1 = hsig(s1a1 + g1a * ((sval.y - mean1) * inv1) + be1a);
            if (colA < 64) {
                int gz = (int)rank * 64 + colA;
                ull pv = f22ull(make_float2(sv0, sv1));
                #pragma unroll
                for (uint r = 0; r < 4; r++) st_cl_b64(&z2g[gz], r, pv);
            } else {
                int uu = (int)rank * 64 + colA - 64;
                float2 h = h2[uu];
                ull pv = f22ull(make_float2(sv0 * h.x, sv1 * h.y));
                #pragma unroll
                for (uint r = 0; r < 4; r++) st_cl_b64(&rh2[uu], r, pv);
            }
        }
        CLUSTER_SYNC();   // S2: rh + z visible everywhere

        // ---- phase B: (r*h) @ U[:, 512+gB] over k-quarter ----
        const ull* rp = (const ull*)rh2 + kq * 64;
        ull b0a = 0, b1a = 0;
        #pragma unroll
        for (int j = 0; j < 64; j += 4) {
            ulonglong2 ra = *(const ulonglong2*)(rp + j);
            ulonglong2 rb = *(const ulonglong2*)(rp + j + 2);
            FMA2(b0a, ra.x, UB[j]);     FMA2(b1a, ra.y, UB[j + 1]);
            FMA2(b0a, rb.x, UB[j + 2]); FMA2(b1a, rb.y, UB[j + 3]);
        }
        float2 g0 = ull2f2(b0a), g1 = ull2f2(b1a);
        float2 accB = make_float2(g0.x + g1.x, g0.y + g1.y);
        if (tid >= 64) cbuf[tid - 64] = accB;
        __syncthreads();

        if (tid < 64) {
            float2 o1 = cbuf[tid], o2 = cbuf[64 + tid], o3 = cbuf[128 + tid];
            float2 sB = make_float2(accB.x + o1.x + o2.x + o3.x,
                                    accB.y + o1.y + o2.y + o3.y);
            ull pv = f22ull(sB);
            #pragma unroll
            for (uint r = 0; r < 4; r++) st_cl_b64(&sBg[gB], r, pv);
            float p0 = sB.x, p1 = sB.y, q0 = p0 * p0, q1 = p1 * p1;
            #pragma unroll
            for (int o = 16; o; o >>= 1) {
                p0 += __shfl_down_sync(0xffffffffu, p0, o);
                p1 += __shfl_down_sync(0xffffffffu, p1, o);
                q0 += __shfl_down_sync(0xffffffffu, q0, o);
                q1 += __shfl_down_sync(0xffffffffu, q1, o);
            }
            if (!lane) { wsl[wid] = make_float2(p0, p1);
                         wsl[4 + wid] = make_float2(q0, q1); }
        }
        __syncthreads();
        if (tid == 0) {
            float2 S = make_float2(wsl[0].x + wsl[1].x, wsl[0].y + wsl[1].y);
            float2 Q = make_float2(wsl[4].x + wsl[5].x, wsl[4].y + wsl[5].y);
            #pragma unroll
            for (uint r = 0; r < 4; r++) {
                st_cl_b64(&pB[rank], r, f22ull(S));
                st_cl_b64(&pB[4 + rank], r, f22ull(Q));
            }
        }
        CLUSTER_SYNC();   // S3: sB + LN-B partials visible everywhere

        // ---- phase C: computed redundantly by ALL CTAs; h stays local ----
        {
            float2 S = make_float2(0, 0), Q = make_float2(0, 0);
            #pragma unroll
            for (int r = 0; r < 4; r++) {
                S.x += pB[r].x; S.y += pB[r].y;
                Q.x += pB[4 + r].x; Q.y += pB[4 + r].y;
            }
            float mean0 = S.x * (1.0f / 256.0f), mean1 = S.y * (1.0f / 256.0f);
            float var0 = fmaxf(Q.x * (1.0f / 256.0f) - mean0 * mean0, 0.0f);
            float var1 = fmaxf(Q.y * (1.0f / 256.0f) - mean1 * mean1, 0.0f);
            float inv0 = 1.0f / (sqrtf(var0 + LN_EPS) + LN_EPS);
            float inv1 = 1.0f / (sqrtf(var1 + LN_EPS) + LN_EPS);
            float2 sB = sBg[uC];
            float hc0 = tanhf(s1c0 + g1c * ((sB.x - mean0) * inv0) + be1c);
            float hc1 = tanhf(s1c1 + g1c * ((sB.y - mean1) * inv1) + be1c);
            float2 z = z2g[uC];
            float2 h = h2[uC];
            float hn0 = z.x * h.x + (1.0f - z.x) * hc0;
            float hn1 = z.y * h.y + (1.0f - z.y) * hc1;
            h2[uC] = make_float2(m0 ? hn0 : h.x, m1 ? hn1 : h.y);
        }
        __syncthreads();   // h2 complete before next phase A (CTA-local)
    }

    if (rank == 0) {
        float2 h = h2[uC];
        out[(size_t)b0 * 512 + uC] = h.x;
        out[(size_t)b1 * 512 + uC] = h.y;
    }
}

// ---------------- launch ---------------------------------------------------
extern "C" void kernel_launch(void* const* d_in, const int* in_sizes, int n_in,
                              void* d_out, int out_size) {
    const int* x           = (const int*)d_in[0];   // token ids (int32)
    const float* emb       = (const float*)d_in[2];
    const float* W         = (const float*)d_in[3];
    const float* Umat      = (const float*)d_in[4];
    const float* bias      = (const float*)d_in[5];
    const float* gammas    = (const float*)d_in[6];
    const float* betas     = (const float*)d_in[7];
    const float* kern      = (const float*)d_in[8];
    float* out             = (float*)d_out;

    float *xe, *s1p;
    cudaGetSymbolAddress((void**)&xe, g_xemb);
    cudaGetSymbolAddress((void**)&s1p, g_s1);

    // 1) embedding gather
    embed_kernel<<<TT * BB, 256>>>(x, emb);
    // 2) s1 = x_emb @ W + b  (M=32768, N=768, K=256), then LN in place
    gemm128<<<dim3(N3 / 128, TT * BB / 128), 256>>>(xe, W, bias, s1p,
                                                    N3, NU, 0);
    ln_kernel<<<TT * BB, 256>>>(gammas, betas);
    // 3) conv as ONE K=768 GEMM with fused max
    encinit_kernel<<<BB, 256>>>();
    gemm128<<<dim3(NU / 128, (510 * BB) / 128), 256>>>(xe, kern, nullptr,
                                                       nullptr, NU, 3 * NU, 1);
    decode_kernel<<<BB, 256>>>(out);
    // 4) recurrence: cluster-parallel, U register-resident
    rec_kernel<<<128, 256>>>(x, Umat, s1p, gammas, betas, out);
}

// round 6
// speedup vs baseline: 2.6069x; 1.1630x over previous
#include <cuda_runtime.h>
#include <math.h>

// Problem constants (fixed shapes)
#define BB 64      // batch
#define TT 512     // time / bucket_size
#define NU 256     // units
#define N3 768     // 3*units
#define LN_EPS 1e-5f

typedef unsigned long long ull;
typedef unsigned int uint;

// ---------------- scratch (static device arrays; no runtime allocation) ----
__device__ float g_xemb[TT * BB * NU];   // [t][b][c]   33.5 MB
__device__ float g_s1[TT * BB * N3];     // [t][b][768] 100 MB (LN'd in place)
__device__ uint  g_enc[BB * NU];         // encoded running max for conv

// ---------------- small helpers -------------------------------------------
__device__ __forceinline__ uint enc_f(float v) {
    uint u = __float_as_uint(v);
    return ((int)u < 0) ? ~u : (u | 0x80000000u);
}
__device__ __forceinline__ float dec_f(uint e) {
    uint u = (e & 0x80000000u) ? (e ^ 0x80000000u) : ~e;
    return __uint_as_float(u);
}
__device__ __forceinline__ float hsig(float v) {
    return fminf(fmaxf(0.2f * v + 0.5f, 0.0f), 1.0f);
}
__device__ __forceinline__ float2 ull2f2(ull v) {
    float2 r;
    asm("mov.b64 {%0, %1}, %2;" : "=f"(r.x), "=f"(r.y) : "l"(v));
    return r;
}
__device__ __forceinline__ ull f22ull(float2 v) {
    ull r;
    asm("mov.b64 %0, {%1, %2};" : "=l"(r) : "f"(v.x), "f"(v.y));
    return r;
}
// packed fma: acc.{lo,hi} += hk.{lo,hi} * u
#define FMA2(acc, hk, uval) do {                                          \
    ull _pu;                                                              \
    asm("mov.b64 %0, {%1, %1};" : "=l"(_pu) : "f"(uval));                 \
    asm("fma.rn.f32x2 %0, %1, %2, %0;" : "+l"(acc) : "l"(hk), "l"(_pu));  \
} while (0)

__device__ __forceinline__ uint ctarank() {
    uint r; asm("mov.u32 %0, %%cluster_ctarank;" : "=r"(r)); return r;
}
__device__ __forceinline__ void st_cl_b64(void* laddr, uint r, ull v) {
    uint la = (uint)__cvta_generic_to_shared(laddr);
    asm volatile(
        "{ .reg .b32 ra; mapa.shared::cluster.u32 ra, %0, %1; "
        "st.shared::cluster.b64 [ra], %2; }"
        :: "r"(la), "r"(r), "l"(v) : "memory");
}
#define CLUSTER_SYNC() do {                                        \
    asm volatile("barrier.cluster.arrive.aligned;" ::: "memory");  \
    asm volatile("barrier.cluster.wait.aligned;" ::: "memory");    \
} while (0)

__device__ __forceinline__ uint f2tf32(float v) {
    uint r;
    asm("cvt.rna.tf32.f32 %0, %1;" : "=r"(r) : "f"(v));
    return r;
}

// ---------------- embedding gather ----------------------------------------
__global__ void embed_kernel(const int* __restrict__ x,
                             const float* __restrict__ emb) {
    int idx = blockIdx.x * 256 + threadIdx.x;
    int c = idx & 255;
    int b = (idx >> 8) & 63;
    int t = idx >> 14;
    int row = x[(size_t)b * TT + t];
    g_xemb[idx] = emb[(size_t)row * NU + c];
}

__global__ void encinit_kernel() {
    g_enc[blockIdx.x * 256 + threadIdx.x] = enc_f(-INFINITY);
}
__global__ void decode_kernel(float* __restrict__ out) {
    int f = threadIdx.x;           // 256
    int b = blockIdx.x;            // 64
    out[(size_t)b * 512 + 256 + f] = dec_f(g_enc[b * 256 + f]);
}

// ---------------- 128x128 tf32 tensor-core GEMM ----------------------------
// C(MxN) = A(MxK) * B(KxN).  A uses g_xemb segment addressing:
//   A[row,k] = A[row*256 + (k>>8)*16384 + (k&255)]  (plain row-major if K=256;
//   realizes the width-3 conv as one GEMM when K=768).
// BK=16, 256 threads = 8 warps (2 m x 4 n), warp tile 64x32 via m16n8k8.
// smem k-major, stride 136 (= 8 mod 32 banks -> conflict-free frags).
#define TSTR 136
__global__ void __launch_bounds__(256)
gemm_tc(const float* __restrict__ A, const float* __restrict__ B,
        const float* __restrict__ bias, float* __restrict__ C,
        int N, int K, int domax) {
    __shared__ uint As[2][16 * TSTR];
    __shared__ uint Bs[2][16 * TSTR];

    int tid = threadIdx.x;
    int lane = tid & 31, warp = tid >> 5;
    int wm = warp >> 2, wn = warp & 3;           // warp grid 2x4
    int lk = lane & 3, lg = lane >> 2;
    int r0 = blockIdx.y * 128, c0 = blockIdx.x * 128;

    // staging roles
    int am = tid >> 1, akq = (tid & 1) * 8;      // A: row am, 8 k's
    int bk = tid >> 4, bn = (tid & 15) * 8;      // B: k row bk, 8 n's

    float c[4][4][4];
    #pragma unroll
    for (int i = 0; i < 4; i++)
        #pragma unroll
        for (int j = 0; j < 4; j++)
            #pragma unroll
            for (int q = 0; q < 4; q++) c[i][j][q] = 0.0f;

    const float* Arow = A + (size_t)(r0 + am) * 256;

    float aL[8], bL[8];
    {   // prefetch tile 0
        int fk = akq;
        int ab = ((fk >> 8) << 14) + (fk & 255);
        float4 v0 = *(const float4*)&Arow[ab];
        float4 v1 = *(const float4*)&Arow[ab + 4];
        aL[0]=v0.x; aL[1]=v0.y; aL[2]=v0.z; aL[3]=v0.w;
        aL[4]=v1.x; aL[5]=v1.y; aL[6]=v1.z; aL[7]=v1.w;
        const float* Bp = &B[(size_t)bk * N + c0 + bn];
        float4 w0 = *(const float4*)Bp;
        float4 w1 = *(const float4*)(Bp + 4);
        bL[0]=w0.x; bL[1]=w0.y; bL[2]=w0.z; bL[3]=w0.w;
        bL[4]=w1.x; bL[5]=w1.y; bL[6]=w1.z; bL[7]=w1.w;
        #pragma unroll
        for (int i = 0; i < 8; i++) {
            As[0][(akq + i) * TSTR + am] = f2tf32(aL[i]);
            Bs[0][bk * TSTR + bn + i]    = f2tf32(bL[i]);
        }
    }
    __syncthreads();

    int buf = 0;
    for (int k0 = 0; k0 < K; k0 += 16) {
        bool more = (k0 + 16) < K;
        if (more) {
            int fk = k0 + 16 + akq;
            int ab = ((fk >> 8) << 14) + (fk & 255);
            float4 v0 = *(const float4*)&Arow[ab];
            float4 v1 = *(const float4*)&Arow[ab + 4];
            aL[0]=v0.x; aL[1]=v0.y; aL[2]=v0.z; aL[3]=v0.w;
            aL[4]=v1.x; aL[5]=v1.y; aL[6]=v1.z; aL[7]=v1.w;
            const float* Bp = &B[(size_t)(k0 + 16 + bk) * N + c0 + bn];
            float4 w0 = *(const float4*)Bp;
            float4 w1 = *(const float4*)(Bp + 4);
            bL[0]=w0.x; bL[1]=w0.y; bL[2]=w0.z; bL[3]=w0.w;
            bL[4]=w1.x; bL[5]=w1.y; bL[6]=w1.z; bL[7]=w1.w;
        }
        const uint* as = As[buf];
        const uint* bs = Bs[buf];
        #pragma unroll
        for (int kt = 0; kt < 2; kt++) {
            int kb = kt * 8;
            uint af[4][4], bf[4][2];
            #pragma unroll
            for (int mt = 0; mt < 4; mt++) {
                int m = wm * 64 + mt * 16 + lg;
                af[mt][0] = as[(kb + lk) * TSTR + m];
                af[mt][1] = as[(kb + lk) * TSTR + m + 8];
                af[mt][2] = as[(kb + lk + 4) * TSTR + m];
                af[mt][3] = as[(kb + lk + 4) * TSTR + m + 8];
            }
            #pragma unroll
            for (int nt = 0; nt < 4; nt++) {
                int n = wn * 32 + nt * 8 + lg;
                bf[nt][0] = bs[(kb + lk) * TSTR + n];
                bf[nt][1] = bs[(kb + lk + 4) * TSTR + n];
            }
            #pragma unroll
            for (int mt = 0; mt < 4; mt++)
                #pragma unroll
                for (int nt = 0; nt < 4; nt++)
                    asm("mma.sync.aligned.m16n8k8.row.col.f32.tf32.tf32.f32 "
                        "{%0,%1,%2,%3}, {%4,%5,%6,%7}, {%8,%9}, {%0,%1,%2,%3};"
                        : "+f"(c[mt][nt][0]), "+f"(c[mt][nt][1]),
                          "+f"(c[mt][nt][2]), "+f"(c[mt][nt][3])
                        : "r"(af[mt][0]), "r"(af[mt][1]),
                          "r"(af[mt][2]), "r"(af[mt][3]),
                          "r"(bf[nt][0]), "r"(bf[nt][1]));
        }
        if (more) {
            #pragma unroll
            for (int i = 0; i < 8; i++) {
                As[buf ^ 1][(akq + i) * TSTR + am] = f2tf32(aL[i]);
                Bs[buf ^ 1][bk * TSTR + bn + i]    = f2tf32(bL[i]);
            }
        }
        __syncthreads();
        buf ^= 1;
    }

    // epilogue: c0,c1 at (row lg, cols 2*lk, 2*lk+1); c2,c3 at row lg+8
    #pragma unroll
    for (int mt = 0; mt < 4; mt++) {
        #pragma unroll
        for (int nt = 0; nt < 4; nt++) {
            int row0 = r0 + wm * 64 + mt * 16 + lg;
            int col  = c0 + wn * 32 + nt * 8 + lk * 2;
            float v0 = c[mt][nt][0], v1 = c[mt][nt][1];
            float v2 = c[mt][nt][2], v3 = c[mt][nt][3];
            if (bias) {
                float bb0 = bias[col], bb1 = bias[col + 1];
                v0 += bb0; v1 += bb1; v2 += bb0; v3 += bb1;
            }
            if (C) {
                *(float2*)&C[(size_t)row0 * N + col] = make_float2(v0, v1);
                *(float2*)&C[(size_t)(row0 + 8) * N + col] = make_float2(v2, v3);
            }
            if (domax) {
                int ba = row0 & 63, bb = (row0 + 8) & 63;
                atomicMax(&g_enc[ba * 256 + col], enc_f(v0));
                atomicMax(&g_enc[ba * 256 + col + 1], enc_f(v1));
                atomicMax(&g_enc[bb * 256 + col], enc_f(v2));
                atomicMax(&g_enc[bb * 256 + col + 1], enc_f(v3));
            }
        }
    }
}

// ---------------- row LayerNorm over 768 cols, in place on g_s1 ------------
__global__ void ln_kernel(const float* __restrict__ gam,
                          const float* __restrict__ bet) {
    int row = blockIdx.x;
    float* p = g_s1 + (size_t)row * N3;
    int tid = threadIdx.x;
    float v0 = p[tid], v1 = p[tid + 256], v2 = p[tid + 512];
    float s = v0 + v1 + v2;
    float q = v0 * v0 + v1 * v1 + v2 * v2;
    __shared__ float rs[8], rq[8];
    __shared__ float tot[2];
    int lane = tid & 31, w = tid >> 5;
    #pragma unroll
    for (int o = 16; o; o >>= 1) {
        s += __shfl_down_sync(0xffffffffu, s, o);
        q += __shfl_down_sync(0xffffffffu, q, o);
    }
    if (!lane) { rs[w] = s; rq[w] = q; }
    __syncthreads();
    if (tid == 0) {
        float S = 0, Q = 0;
        for (int i = 0; i < 8; i++) { S += rs[i]; Q += rq[i]; }
        tot[0] = S; tot[1] = Q;
    }
    __syncthreads();
    float mean = tot[0] * (1.0f / 768.0f);
    float var = fmaxf(tot[1] * (1.0f / 768.0f) - mean * mean, 0.0f);
    float inv = 1.0f / (sqrtf(var + LN_EPS) + LN_EPS);
    p[tid]       = gam[tid]       * ((v0 - mean) * inv) + bet[tid];
    p[tid + 256] = gam[tid + 256] * ((v1 - mean) * inv) + bet[tid + 256];
    p[tid + 512] = gam[tid + 512] * ((v2 - mean) * inv) + bet[tid + 512];
}

// =============== recurrence: 32 clusters x 4 CTAs, U in REGISTERS ==========
__global__ void __launch_bounds__(256, 1) __cluster_dims__(4, 1, 1)
rec_kernel(const int* __restrict__ x, const float* __restrict__ Umat,
           const float* __restrict__ s1, const float* __restrict__ gammas,
           const float* __restrict__ betas, float* __restrict__ out) {
    __shared__ __align__(16) float2 h2[256];    // h, local authoritative copy
    __shared__ __align__(16) float2 rh2[256];   // r*h (cluster-broadcast)
    __shared__ __align__(16) float2 z2g[256];   // z gates (cluster-broadcast)
    __shared__ __align__(16) float2 sBg[256];   // hc presums (cluster-broadcast)
    __shared__ __align__(16) float2 cbuf[192];  // intra-CTA partial exchange
    __shared__ float2 wsl[8];                   // warp reduction slots
    __shared__ float2 pA[8];                    // LN-A partials per rank (S,Q)
    __shared__ float2 pB[8];                    // LN-B partials per rank (S,Q)

    int tid  = threadIdx.x;
    uint rank = ctarank();
    int cid  = blockIdx.x >> 2;
    int b0   = cid * 2, b1 = b0 + 1;
    int lane = tid & 31, wid = tid >> 5;

    int colA  = tid & 127;
    int khalf = tid >> 7;
    int gA = (colA < 64) ? ((int)rank * 64 + colA)
                         : (256 + (int)rank * 64 + (colA - 64));
    float g1a = gammas[N3 + gA], be1a = betas[N3 + gA];
    int uC = tid;                                 // phase-C unit (0..255)
    float g1c = gammas[N3 + 512 + uC], be1c = betas[N3 + 512 + uC];
    int uB = tid & 63, kq = tid >> 6;
    int gB = (int)rank * 64 + uB;

    // ---- one-time: U slices into registers ----
    float UA[128];
    #pragma unroll
    for (int k = 0; k < 128; k++)
        UA[k] = Umat[(size_t)(khalf * 128 + k) * N3 + gA];
    float UB[64];
    #pragma unroll
    for (int j = 0; j < 64; j++)
        UB[j] = Umat[(size_t)(kq * 64 + j) * N3 + 512 + gB];

    h2[tid] = make_float2(0.0f, 0.0f);
    __syncthreads();
    CLUSTER_SYNC();

    for (int t = 0; t < TT; t++) {
        // prefetch s1 / masks (consumed late)
        const float* s1r0 = s1 + ((size_t)t * 64 + b0) * N3;
        const float* s1r1 = s1r0 + N3;
        float s1a0 = 0.0f, s1a1 = 0.0f;
        if (tid < 128) { s1a0 = s1r0[gA]; s1a1 = s1r1[gA]; }
        float s1c0 = s1r0[512 + uC], s1c1 = s1r1[512 + uC];
        int m0 = x[(size_t)b0 * TT + t], m1 = x[(size_t)b1 * TT + t];

        // ---- phase A: h @ U[:, gA] over k-half (U in regs, h broadcast) --
        const ull* hp = (const ull*)h2 + khalf * 128;
        ull a0 = 0, a1 = 0, a2 = 0, a3 = 0;
        #pragma unroll
        for (int k = 0; k < 128; k += 4) {
            ulonglong2 ha = *(const ulonglong2*)(hp + k);
            ulonglong2 hb = *(const ulonglong2*)(hp + k + 2);
            FMA2(a0, ha.x, UA[k]);     FMA2(a1, ha.y, UA[k + 1]);
            FMA2(a2, hb.x, UA[k + 2]); FMA2(a3, hb.y, UA[k + 3]);
        }
        float2 f0 = ull2f2(a0), f1 = ull2f2(a1);
        float2 f2v = ull2f2(a2), f3 = ull2f2(a3);
        float2 accA = make_float2((f0.x + f1.x) + (f2v.x + f3.x),
                                  (f0.y + f1.y) + (f2v.y + f3.y));
        if (tid >= 128) cbuf[tid - 128] = accA;
        __syncthreads();

        float2 sval = make_float2(0.0f, 0.0f);
        if (tid < 128) {
            float2 oth = cbuf[tid];
            sval.x = accA.x + oth.x; sval.y = accA.y + oth.y;
            float p0 = sval.x, p1 = sval.y;
            float q0 = p0 * p0, q1 = p1 * p1;
            #pragma unroll
            for (int o = 16; o; o >>= 1) {
                p0 += __shfl_down_sync(0xffffffffu, p0, o);
                p1 += __shfl_down_sync(0xffffffffu, p1, o);
                q0 += __shfl_down_sync(0xffffffffu, q0, o);
                q1 += __shfl_down_sync(0xffffffffu, q1, o);
            }
            if (!lane) { wsl[wid] = make_float2(p0, p1);
                         wsl[4 + wid] = make_float2(q0, q1); }
        }
        __syncthreads();
        if (tid == 0) {
            float2 S = make_float2(0, 0), Q = make_float2(0, 0);
            #pragma unroll
            for (int w = 0; w < 4; w++) {
                S.x += wsl[w].x; S.y += wsl[w].y;
                Q.x += wsl[4 + w].x; Q.y += wsl[4 + w].y;
            }
            #pragma unroll
            for (uint r = 0; r < 4; r++) {
                st_cl_b64(&pA[rank], r, f22ull(S));
                st_cl_b64(&pA[4 + rank], r, f22ull(Q));
            }
        }
        CLUSTER_SYNC();   // S1: LN-A partials visible everywhere

        // ---- gate: z broadcast, rh broadcast ----
        if (tid < 128) {
            float2 S = make_float2(0, 0), Q = make_float2(0, 0);
            #pragma unroll
            for (int r = 0; r < 4; r++) {
                S.x += pA[r].x; S.y += pA[r].y;
                Q.x += pA[4 + r].x; Q.y += pA[4 + r].y;
            }
            float mean0 = S.x * (1.0f / 512.0f), mean1 = S.y * (1.0f / 512.0f);
            float var0 = fmaxf(Q.x * (1.0f / 512.0f) - mean0 * mean0, 0.0f);
            float var1 = fmaxf(Q.y * (1.0f / 512.0f) - mean1 * mean1, 0.0f);
            float inv0 = 1.0f / (sqrtf(var0 + LN_EPS) + LN_EPS);
            float inv1 = 1.0f / (sqrtf(var1 + LN_EPS) + LN_EPS);
            float sv0 = hsig(s1a0 + g1a * ((sval.x - mean0) * inv0) + be1a);
            float sv1 = hsig(s1a1 + g1a * ((sval.y - mean1) * inv1) + be1a);
            if (colA < 64) {
                int gz = (int)rank * 64 + colA;
                ull pv = f22ull(make_float2(sv0, sv1));
                #pragma unroll
                for (uint r = 0; r < 4; r++) st_cl_b64(&z2g[gz], r, pv);
            } else {
                int uu = (int)rank * 64 + colA - 64;
                float2 h = h2[uu];
                ull pv = f22ull(make_float2(sv0 * h.x, sv1 * h.y));
                #pragma unroll
                for (uint r = 0; r < 4; r++) st_cl_b64(&rh2[uu], r, pv);
            }
        }
        CLUSTER_SYNC();   // S2: rh + z visible everywhere

        // ---- phase B: (r*h) @ U[:, 512+gB] over k-quarter ----
        const ull* rp = (const ull*)rh2 + kq * 64;
        ull b0a = 0, b1a = 0;
        #pragma unroll
        for (int j = 0; j < 64; j += 4) {
            ulonglong2 ra = *(const ulonglong2*)(rp + j);
            ulonglong2 rb = *(const ulonglong2*)(rp + j + 2);
            FMA2(b0a, ra.x, UB[j]);     FMA2(b1a, ra.y, UB[j + 1]);
            FMA2(b0a, rb.x, UB[j + 2]); FMA2(b1a, rb.y, UB[j + 3]);
        }
        float2 g0 = ull2f2(b0a), g1 = ull2f2(b1a);
        float2 accB = make_float2(g0.x + g1.x, g0.y + g1.y);
        if (tid >= 64) cbuf[tid - 64] = accB;
        __syncthreads();

        if (tid < 64) {
            float2 o1 = cbuf[tid], o2 = cbuf[64 + tid], o3 = cbuf[128 + tid];
            float2 sB = make_float2(accB.x + o1.x + o2.x + o3.x,
                                    accB.y + o1.y + o2.y + o3.y);
            ull pv = f22ull(sB);
            #pragma unroll
            for (uint r = 0; r < 4; r++) st_cl_b64(&sBg[gB], r, pv);
            float p0 = sB.x, p1 = sB.y, q0 = p0 * p0, q1 = p1 * p1;
            #pragma unroll
            for (int o = 16; o; o >>= 1) {
                p0 += __shfl_down_sync(0xffffffffu, p0, o);
                p1 += __shfl_down_sync(0xffffffffu, p1, o);
                q0 += __shfl_down_sync(0xffffffffu, q0, o);
                q1 += __shfl_down_sync(0xffffffffu, q1, o);
            }
            if (!lane) { wsl[wid] = make_float2(p0, p1);
                         wsl[4 + wid] = make_float2(q0, q1); }
        }
        __syncthreads();
        if (tid == 0) {
            float2 S = make_float2(wsl[0].x + wsl[1].x, wsl[0].y + wsl[1].y);
            float2 Q = make_float2(wsl[4].x + wsl[5].x, wsl[4].y + wsl[5].y);
            #pragma unroll
            for (uint r = 0; r < 4; r++) {
                st_cl_b64(&pB[rank], r, f22ull(S));
                st_cl_b64(&pB[4 + rank], r, f22ull(Q));
            }
        }
        CLUSTER_SYNC();   // S3: sB + LN-B partials visible everywhere

        // ---- phase C: computed redundantly by ALL CTAs; h stays local ----
        {
            float2 S = make_float2(0, 0), Q = make_float2(0, 0);
            #pragma unroll
            for (int r = 0; r < 4; r++) {
                S.x += pB[r].x; S.y += pB[r].y;
                Q.x += pB[4 + r].x; Q.y += pB[4 + r].y;
            }
            float mean0 = S.x * (1.0f / 256.0f), mean1 = S.y * (1.0f / 256.0f);
            float var0 = fmaxf(Q.x * (1.0f / 256.0f) - mean0 * mean0, 0.0f);
            float var1 = fmaxf(Q.y * (1.0f / 256.0f) - mean1 * mean1, 0.0f);
            float inv0 = 1.0f / (sqrtf(var0 + LN_EPS) + LN_EPS);
            float inv1 = 1.0f / (sqrtf(var1 + LN_EPS) + LN_EPS);
            float2 sB = sBg[uC];
            float hc0 = tanhf(s1c0 + g1c * ((sB.x - mean0) * inv0) + be1c);
            float hc1 = tanhf(s1c1 + g1c * ((sB.y - mean1) * inv1) + be1c);
            float2 z = z2g[uC];
            float2 h = h2[uC];
            float hn0 = z.x * h.x + (1.0f - z.x) * hc0;
            float hn1 = z.y * h.y + (1.0f - z.y) * hc1;
            h2[uC] = make_float2(m0 ? hn0 : h.x, m1 ? hn1 : h.y);
        }
        __syncthreads();   // h2 complete before next phase A (CTA-local)
    }

    if (rank == 0) {
        float2 h = h2[uC];
        out[(size_t)b0 * 512 + uC] = h.x;
        out[(size_t)b1 * 512 + uC] = h.y;
    }
}

// ---------------- launch ---------------------------------------------------
extern "C" void kernel_launch(void* const* d_in, const int* in_sizes, int n_in,
                              void* d_out, int out_size) {
    const int* x           = (const int*)d_in[0];   // token ids (int32)
    const float* emb       = (const float*)d_in[2];
    const float* W         = (const float*)d_in[3];
    const float* Umat      = (const float*)d_in[4];
    const float* bias      = (const float*)d_in[5];
    const float* gammas    = (const float*)d_in[6];
    const float* betas     = (const float*)d_in[7];
    const float* kern      = (const float*)d_in[8];
    float* out             = (float*)d_out;

    float *xe, *s1p;
    cudaGetSymbolAddress((void**)&xe, g_xemb);
    cudaGetSymbolAddress((void**)&s1p, g_s1);

    // 1) embedding gather
    embed_kernel<<<TT * BB, 256>>>(x, emb);
    // 2) s1 = x_emb @ W + b  (M=32768, N=768, K=256), then LN in place
    gemm_tc<<<dim3(N3 / 128, TT * BB / 128), 256>>>(xe, W, bias, s1p,
                                                    N3, NU, 0);
    ln_kernel<<<TT * BB, 256>>>(gammas, betas);
    // 3) conv as ONE K=768 GEMM (M = 510*64 = 32640 = 255*128) with fused max
    encinit_kernel<<<BB, 256>>>();
    gemm_tc<<<dim3(NU / 128, (510 * BB) / 128), 256>>>(xe, kern, nullptr,
                                                       nullptr, NU, 3 * NU, 1);
    decode_kernel<<<BB, 256>>>(out);
    // 4) recurrence: cluster-parallel, U register-resident
    rec_kernel<<<128, 256>>>(x, Umat, s1p, gammas, betas, out);
}